// round 1
// baseline (speedup 1.0000x reference)
#include <cuda_runtime.h>
#include <math.h>

// Problem constants
#define BB 2
#define TT 2048
#define HH 1024
#define NHH 16
#define DD 64
#define FFF 4096
#define LL 6
#define MM (BB*TT)   // 4096 rows

// ---------------- scratch activations (device globals; no allocation) ------
__device__ float g_x[MM*HH];
__device__ float g_q[MM*HH];
__device__ float g_k[MM*HH];
__device__ float g_v[MM*HH];
__device__ float g_o[MM*HH];
__device__ float g_t[MM*HH];
__device__ float g_h[MM*FFF];

// ---------------- generic tiled GEMM: C = epi(A*B + bias [+resid]) --------
// A: MxK row-major, B: KxN row-major, bias: N, resid: MxN
// epi: 0 = bias, 1 = bias+gelu(exact), 2 = bias+resid
#define BM 128
#define BN 128
#define BK 16

__global__ __launch_bounds__(256) void gemm_kernel(
    const float* __restrict__ A, const float* __restrict__ B,
    const float* __restrict__ bias, const float* __restrict__ resid,
    float* __restrict__ C, int M, int N, int K, int epi)
{
    __shared__ float As[BK][BM + 4];
    __shared__ float Bs[BK][BN + 4];

    const int tid = threadIdx.x;
    const int tx = tid & 15;        // 0..15  -> columns
    const int ty = tid >> 4;        // 0..15  -> rows
    const int bm = blockIdx.y * BM;
    const int bn = blockIdx.x * BN;

    float acc[8][8];
    #pragma unroll
    for (int i = 0; i < 8; i++)
        #pragma unroll
        for (int j = 0; j < 8; j++) acc[i][j] = 0.f;

    const float* Aptr = A + (size_t)bm * K;
    const float* Bptr = B + bn;

    for (int k0 = 0; k0 < K; k0 += BK) {
        // Load A tile [BM x BK], store transposed into As[k][m]
        #pragma unroll
        for (int t = 0; t < 2; t++) {
            int idx = tid + t * 256;          // 0..511
            int row = idx >> 2;               // 0..127
            int c4  = (idx & 3) * 4;          // 0,4,8,12
            float4 v = *(const float4*)(Aptr + (size_t)row * K + k0 + c4);
            As[c4 + 0][row] = v.x;
            As[c4 + 1][row] = v.y;
            As[c4 + 2][row] = v.z;
            As[c4 + 3][row] = v.w;
        }
        // Load B tile [BK x BN]
        #pragma unroll
        for (int t = 0; t < 2; t++) {
            int idx = tid + t * 256;          // 0..511
            int row = idx >> 5;               // 0..15
            int c4  = (idx & 31) * 4;         // 0..124
            *(float4*)&Bs[row][c4] =
                *(const float4*)(Bptr + (size_t)(k0 + row) * N + c4);
        }
        __syncthreads();

        #pragma unroll
        for (int kk = 0; kk < BK; kk++) {
            float4 a0 = *(const float4*)&As[kk][ty * 4];
            float4 a1 = *(const float4*)&As[kk][64 + ty * 4];
            float4 b0 = *(const float4*)&Bs[kk][tx * 4];
            float4 b1 = *(const float4*)&Bs[kk][64 + tx * 4];
            float a[8] = {a0.x, a0.y, a0.z, a0.w, a1.x, a1.y, a1.z, a1.w};
            float b[8] = {b0.x, b0.y, b0.z, b0.w, b1.x, b1.y, b1.z, b1.w};
            #pragma unroll
            for (int i = 0; i < 8; i++)
                #pragma unroll
                for (int j = 0; j < 8; j++)
                    acc[i][j] = fmaf(a[i], b[j], acc[i][j]);
        }
        __syncthreads();
    }

    // Epilogue
    #pragma unroll
    for (int i = 0; i < 8; i++) {
        int row = bm + ((i < 4) ? (ty * 4 + i) : (64 + ty * 4 + (i - 4)));
        #pragma unroll
        for (int jh = 0; jh < 2; jh++) {
            int col = bn + ((jh == 0) ? (tx * 4) : (64 + tx * 4));
            float4 bv = *(const float4*)(bias + col);
            float r[4];
            r[0] = acc[i][jh * 4 + 0] + bv.x;
            r[1] = acc[i][jh * 4 + 1] + bv.y;
            r[2] = acc[i][jh * 4 + 2] + bv.z;
            r[3] = acc[i][jh * 4 + 3] + bv.w;
            if (epi == 1) {
                #pragma unroll
                for (int u = 0; u < 4; u++)
                    r[u] = 0.5f * r[u] * (1.0f + erff(r[u] * 0.70710678118654752f));
            } else if (epi == 2) {
                float4 rv = *(const float4*)(resid + (size_t)row * N + col);
                r[0] += rv.x; r[1] += rv.y; r[2] += rv.z; r[3] += rv.w;
            }
            *(float4*)(C + (size_t)row * N + col) = make_float4(r[0], r[1], r[2], r[3]);
        }
    }
}

// ---------------- causal flash attention (fp32, D=64) ----------------------
// Q,K,V,O laid out [B,T,H] with head h occupying columns [h*64, h*64+64)
// grid: (T/64, NH, B), block: 64 threads (one query per thread)
__global__ __launch_bounds__(64) void attn_kernel(
    const float* __restrict__ Q, const float* __restrict__ K,
    const float* __restrict__ V, float* __restrict__ O)
{
    __shared__ float Ks[64][64];
    __shared__ float Vs[64][64];
    __shared__ float Ss[64][64];   // Ss[j][query_tid] -> conflict-free

    const int qt  = blockIdx.x;
    const int h   = blockIdx.y;
    const int b   = blockIdx.z;
    const int tid = threadIdx.x;
    const int qglob = qt * 64 + tid;

    const float* qrow = Q + ((size_t)(b * TT + qglob)) * HH + h * DD;

    float q[64], o[64];
    #pragma unroll
    for (int d4 = 0; d4 < 16; d4++) {
        float4 v = *(const float4*)(qrow + d4 * 4);
        q[d4 * 4 + 0] = v.x; q[d4 * 4 + 1] = v.y;
        q[d4 * 4 + 2] = v.z; q[d4 * 4 + 3] = v.w;
    }
    #pragma unroll
    for (int d = 0; d < 64; d++) o[d] = 0.f;

    float m = -1e30f, l = 0.f;

    for (int kt = 0; kt <= qt; kt++) {
        __syncthreads();   // previous tile fully consumed
        // load K/V tiles (64x64 each): 64 threads x 16 float4 each
        for (int idx = tid; idx < 64 * 16; idx += 64) {
            int j  = idx >> 4;
            int c4 = (idx & 15) * 4;
            size_t base = ((size_t)(b * TT + kt * 64 + j)) * HH + h * DD + c4;
            *(float4*)&Ks[j][c4] = *(const float4*)(K + base);
            *(float4*)&Vs[j][c4] = *(const float4*)(V + base);
        }
        __syncthreads();

        const int jmax = (kt == qt) ? (tid + 1) : 64;
        float tmax = -1e30f;
        for (int j = 0; j < jmax; j++) {
            float s0 = 0.f, s1 = 0.f, s2 = 0.f, s3 = 0.f;
            #pragma unroll
            for (int d4 = 0; d4 < 16; d4++) {
                float4 kv = *(const float4*)&Ks[j][d4 * 4];
                s0 = fmaf(q[d4 * 4 + 0], kv.x, s0);
                s1 = fmaf(q[d4 * 4 + 1], kv.y, s1);
                s2 = fmaf(q[d4 * 4 + 2], kv.z, s2);
                s3 = fmaf(q[d4 * 4 + 3], kv.w, s3);
            }
            float s = (s0 + s1 + s2 + s3) * 0.125f;   // 1/sqrt(64)
            Ss[j][tid] = s;
            tmax = fmaxf(tmax, s);
        }
        float mnew = fmaxf(m, tmax);
        float factor = __expf(m - mnew);
        l *= factor;
        #pragma unroll
        for (int d = 0; d < 64; d++) o[d] *= factor;
        for (int j = 0; j < jmax; j++) {
            float p = __expf(Ss[j][tid] - mnew);
            l += p;
            #pragma unroll
            for (int d4 = 0; d4 < 16; d4++) {
                float4 vv = *(const float4*)&Vs[j][d4 * 4];
                o[d4 * 4 + 0] = fmaf(p, vv.x, o[d4 * 4 + 0]);
                o[d4 * 4 + 1] = fmaf(p, vv.y, o[d4 * 4 + 1]);
                o[d4 * 4 + 2] = fmaf(p, vv.z, o[d4 * 4 + 2]);
                o[d4 * 4 + 3] = fmaf(p, vv.w, o[d4 * 4 + 3]);
            }
        }
        m = mnew;
    }

    const float inv = 1.f / l;
    float* orow = O + ((size_t)(b * TT + qglob)) * HH + h * DD;
    #pragma unroll
    for (int d4 = 0; d4 < 16; d4++) {
        float4 v = make_float4(o[d4 * 4 + 0] * inv, o[d4 * 4 + 1] * inv,
                               o[d4 * 4 + 2] * inv, o[d4 * 4 + 3] * inv);
        *(float4*)(orow + d4 * 4) = v;
    }
}

// ---------------- LayerNorm over last dim (1024) ---------------------------
// grid: M rows, block: 256 threads (4 floats each)
__global__ __launch_bounds__(256) void ln_kernel(
    const float* __restrict__ in, const float* __restrict__ gamma,
    const float* __restrict__ beta, float* __restrict__ out)
{
    __shared__ float red[256];
    const int row = blockIdx.x;
    const int tid = threadIdx.x;
    const float* p = in + (size_t)row * HH;

    float4 v = *(const float4*)(p + tid * 4);
    float s = v.x + v.y + v.z + v.w;
    red[tid] = s;
    __syncthreads();
    #pragma unroll
    for (int off = 128; off > 0; off >>= 1) {
        if (tid < off) red[tid] += red[tid + off];
        __syncthreads();
    }
    const float mean = red[0] * (1.0f / HH);
    __syncthreads();

    float dx = v.x - mean, dy = v.y - mean, dz = v.z - mean, dw = v.w - mean;
    red[tid] = dx * dx + dy * dy + dz * dz + dw * dw;
    __syncthreads();
    #pragma unroll
    for (int off = 128; off > 0; off >>= 1) {
        if (tid < off) red[tid] += red[tid + off];
        __syncthreads();
    }
    const float var = red[0] * (1.0f / HH);
    const float rstd = rsqrtf(var + 1e-5f);

    float4 g = *(const float4*)(gamma + tid * 4);
    float4 be = *(const float4*)(beta + tid * 4);
    float4 r;
    r.x = dx * rstd * g.x + be.x;
    r.y = dy * rstd * g.y + be.y;
    r.z = dz * rstd * g.z + be.z;
    r.w = dw * rstd * g.w + be.w;
    *(float4*)(out + (size_t)row * HH + tid * 4) = r;
}

// ---------------- launcher -------------------------------------------------
extern "C" void kernel_launch(void* const* d_in, const int* in_sizes, int n_in,
                              void* d_out, int out_size)
{
    const float* Wq  = (const float*)d_in[1];
    const float* bq  = (const float*)d_in[2];
    const float* Wk  = (const float*)d_in[3];
    const float* bk  = (const float*)d_in[4];
    const float* Wv  = (const float*)d_in[5];
    const float* bv  = (const float*)d_in[6];
    const float* Wp  = (const float*)d_in[7];
    const float* bp  = (const float*)d_in[8];
    const float* W1  = (const float*)d_in[9];
    const float* b1  = (const float*)d_in[10];
    const float* W2  = (const float*)d_in[11];
    const float* b2  = (const float*)d_in[12];
    const float* g1w = (const float*)d_in[13];
    const float* be1 = (const float*)d_in[14];
    const float* g2w = (const float*)d_in[15];
    const float* be2 = (const float*)d_in[16];

    float *gx, *gq, *gk, *gv, *go, *gt, *gh;
    cudaGetSymbolAddress((void**)&gx, g_x);
    cudaGetSymbolAddress((void**)&gq, g_q);
    cudaGetSymbolAddress((void**)&gk, g_k);
    cudaGetSymbolAddress((void**)&gv, g_v);
    cudaGetSymbolAddress((void**)&go, g_o);
    cudaGetSymbolAddress((void**)&gt, g_t);
    cudaGetSymbolAddress((void**)&gh, g_h);

    cudaMemcpyAsync(gx, d_in[0], (size_t)MM * HH * sizeof(float),
                    cudaMemcpyDeviceToDevice, 0);

    const dim3 gridH(HH / BN, MM / BM);    // (8, 32)  N=1024
    const dim3 gridF(FFF / BN, MM / BM);   // (32, 32) N=4096
    const dim3 gridA(TT / 64, NHH, BB);    // attention

    for (int l = 0; l < LL; l++) {
        const size_t wo  = (size_t)l * HH * HH;
        const size_t bo  = (size_t)l * HH;
        const size_t w1o = (size_t)l * HH * FFF;
        const size_t b1o = (size_t)l * FFF;
        const size_t w2o = (size_t)l * FFF * HH;

        // QKV projections
        gemm_kernel<<<gridH, 256>>>(gx, Wq + wo, bq + bo, nullptr, gq, MM, HH, HH, 0);
        gemm_kernel<<<gridH, 256>>>(gx, Wk + wo, bk + bo, nullptr, gk, MM, HH, HH, 0);
        gemm_kernel<<<gridH, 256>>>(gx, Wv + wo, bv + bo, nullptr, gv, MM, HH, HH, 0);

        // attention
        attn_kernel<<<gridA, 64>>>(gq, gk, gv, go);

        // output projection + residual, then LN1
        gemm_kernel<<<gridH, 256>>>(go, Wp + wo, bp + bo, gx, gt, MM, HH, HH, 2);
        ln_kernel<<<MM, 256>>>(gt, g1w + bo, be1 + bo, gx);

        // MLP: gelu(x@W1+b1) ; x + h@W2+b2 ; LN2
        gemm_kernel<<<gridF, 256>>>(gx, W1 + w1o, b1 + b1o, nullptr, gh, MM, FFF, HH, 1);
        gemm_kernel<<<gridH, 256>>>(gh, W2 + w2o, b2 + bo, gx, gt, MM, HH, FFF, 2);
        ln_kernel<<<MM, 256>>>(gt, g2w + bo, be2 + bo, gx);
    }

    cudaMemcpyAsync(d_out, gx, (size_t)MM * HH * sizeof(float),
                    cudaMemcpyDeviceToDevice, 0);
}

// round 2
// speedup vs baseline: 1.1252x; 1.1252x over previous
#include <cuda_runtime.h>
#include <cuda_bf16.h>
#include <math.h>
#include <stdint.h>

// Problem constants
#define BB 2
#define TT 2048
#define HH 1024
#define NHH 16
#define DD 64
#define FFF 4096
#define LL 6
#define MM (BB*TT)   // 4096 rows

// ---------------- scratch activations (device globals; no allocation) ------
__device__ float g_x[MM*HH];
__device__ float g_q[MM*HH];
__device__ float g_k[MM*HH];
__device__ float g_v[MM*HH];
__device__ float g_o[MM*HH];
__device__ float g_t[MM*HH];
__device__ float g_h[MM*FFF];

// ---------------- bf16 split helpers --------------------------------------
__device__ __forceinline__ uint32_t pack_bf2(__nv_bfloat16 a, __nv_bfloat16 b) {
    return (uint32_t)__bfloat16_as_ushort(a) | ((uint32_t)__bfloat16_as_ushort(b) << 16);
}
__device__ __forceinline__ void split1(float x, __nv_bfloat16& h, __nv_bfloat16& l) {
    h = __float2bfloat16_rn(x);
    l = __float2bfloat16_rn(x - __bfloat162float(h));
}

// ---------------- GEMM: C = epi(A*B + bias [+resid]) ----------------------
// A: MxK rm, B: KxN rm. epi: 0=bias, 1=bias+gelu, 2=bias+resid
// bf16 double-split on tensor cores (mma.sync m16n8k16), fp32 accumulate.
#define BM 128
#define BN 128
#define BK 32
#define AS_STRIDE 20     // u32 per A row (16 used + 4 pad) -> conflict-free frags
#define BS_STRIDE 136    // u32 per B pair-row (128 used + 8 pad)

__device__ __forceinline__ void mma16816(float c[4], uint32_t a0, uint32_t a1,
                                         uint32_t a2, uint32_t a3,
                                         uint32_t b0, uint32_t b1) {
    asm volatile(
        "mma.sync.aligned.m16n8k16.row.col.f32.bf16.bf16.f32 "
        "{%0,%1,%2,%3}, {%4,%5,%6,%7}, {%8,%9}, {%0,%1,%2,%3};"
        : "+f"(c[0]), "+f"(c[1]), "+f"(c[2]), "+f"(c[3])
        : "r"(a0), "r"(a1), "r"(a2), "r"(a3), "r"(b0), "r"(b1));
}

__global__ __launch_bounds__(256, 2) void gemm_kernel(
    const float* __restrict__ A, const float* __restrict__ B,
    const float* __restrict__ bias, const float* __restrict__ resid,
    float* __restrict__ C, int M, int N, int K, int epi)
{
    __shared__ uint32_t As_hi[BM * AS_STRIDE];
    __shared__ uint32_t As_lo[BM * AS_STRIDE];
    __shared__ uint32_t Bs_hi[(BK/2) * BS_STRIDE];
    __shared__ uint32_t Bs_lo[(BK/2) * BS_STRIDE];

    const int tid    = threadIdx.x;
    const int lane   = tid & 31;
    const int wid    = tid >> 5;
    const int warp_m = wid & 1;      // 0..1 -> 64 rows each
    const int warp_n = wid >> 1;     // 0..3 -> 32 cols each
    const int bm = blockIdx.y * BM;
    const int bn = blockIdx.x * BN;
    const int r  = lane >> 2;        // 0..7
    const int kq = lane & 3;         // 0..3

    float acc[4][4][4];
    #pragma unroll
    for (int i = 0; i < 4; i++)
        #pragma unroll
        for (int j = 0; j < 4; j++)
            #pragma unroll
            for (int u = 0; u < 4; u++) acc[i][j][u] = 0.f;

    for (int k0 = 0; k0 < K; k0 += BK) {
        // ---- load + split A tile [BM x BK] ----
        #pragma unroll
        for (int t = 0; t < 4; t++) {
            int idx = tid + t * 256;            // 0..1023
            int row = idx >> 3;                 // 0..127
            int c4  = (idx & 7) * 4;            // 0..28
            float4 v = *(const float4*)(A + (size_t)(bm + row) * K + k0 + c4);
            __nv_bfloat16 h0,h1,h2,h3,l0,l1,l2,l3;
            split1(v.x,h0,l0); split1(v.y,h1,l1);
            split1(v.z,h2,l2); split1(v.w,h3,l3);
            int base = row * AS_STRIDE + (c4 >> 1);
            As_hi[base]     = pack_bf2(h0,h1);
            As_hi[base + 1] = pack_bf2(h2,h3);
            As_lo[base]     = pack_bf2(l0,l1);
            As_lo[base + 1] = pack_bf2(l2,l3);
        }
        // ---- load + split B tile [BK x BN] (pair-packed along k) ----
        __nv_bfloat16* bsh = (__nv_bfloat16*)Bs_hi;
        __nv_bfloat16* bsl = (__nv_bfloat16*)Bs_lo;
        #pragma unroll
        for (int t = 0; t < 4; t++) {
            int idx  = tid + t * 256;
            int krow = idx >> 5;                // 0..31
            int c4   = (idx & 31) * 4;          // 0..124
            float4 v = *(const float4*)(B + (size_t)(k0 + krow) * N + bn + c4);
            float e[4] = {v.x, v.y, v.z, v.w};
            int base = (krow >> 1) * (BS_STRIDE * 2) + (krow & 1);
            #pragma unroll
            for (int u = 0; u < 4; u++) {
                __nv_bfloat16 h, l;
                split1(e[u], h, l);
                bsh[base + (c4 + u) * 2] = h;
                bsl[base + (c4 + u) * 2] = l;
            }
        }
        __syncthreads();

        #pragma unroll
        for (int kk = 0; kk < 2; kk++) {
            uint32_t a[4][4], b[4][2];
            // A hi fragments
            #pragma unroll
            for (int i = 0; i < 4; i++) {
                int m = warp_m * 64 + i * 16 + r;
                int base = m * AS_STRIDE + kk * 8 + kq;
                a[i][0] = As_hi[base];
                a[i][1] = As_hi[base + 8 * AS_STRIDE];
                a[i][2] = As_hi[base + 4];
                a[i][3] = As_hi[base + 8 * AS_STRIDE + 4];
            }
            // B hi fragments
            #pragma unroll
            for (int j = 0; j < 4; j++) {
                int n = warp_n * 32 + j * 8 + r;
                int base = (kk * 8 + kq) * BS_STRIDE + n;
                b[j][0] = Bs_hi[base];
                b[j][1] = Bs_hi[base + 4 * BS_STRIDE];
            }
            // term 1: Ahi * Bhi
            #pragma unroll
            for (int i = 0; i < 4; i++)
                #pragma unroll
                for (int j = 0; j < 4; j++)
                    mma16816(acc[i][j], a[i][0],a[i][1],a[i][2],a[i][3], b[j][0],b[j][1]);
            // term 2: Ahi * Blo
            {
                uint32_t bl[4][2];
                #pragma unroll
                for (int j = 0; j < 4; j++) {
                    int n = warp_n * 32 + j * 8 + r;
                    int base = (kk * 8 + kq) * BS_STRIDE + n;
                    bl[j][0] = Bs_lo[base];
                    bl[j][1] = Bs_lo[base + 4 * BS_STRIDE];
                }
                #pragma unroll
                for (int i = 0; i < 4; i++)
                    #pragma unroll
                    for (int j = 0; j < 4; j++)
                        mma16816(acc[i][j], a[i][0],a[i][1],a[i][2],a[i][3], bl[j][0],bl[j][1]);
            }
            // term 3: Alo * Bhi (reuse a regs)
            #pragma unroll
            for (int i = 0; i < 4; i++) {
                int m = warp_m * 64 + i * 16 + r;
                int base = m * AS_STRIDE + kk * 8 + kq;
                a[i][0] = As_lo[base];
                a[i][1] = As_lo[base + 8 * AS_STRIDE];
                a[i][2] = As_lo[base + 4];
                a[i][3] = As_lo[base + 8 * AS_STRIDE + 4];
            }
            #pragma unroll
            for (int i = 0; i < 4; i++)
                #pragma unroll
                for (int j = 0; j < 4; j++)
                    mma16816(acc[i][j], a[i][0],a[i][1],a[i][2],a[i][3], b[j][0],b[j][1]);
        }
        __syncthreads();
    }

    // ---- epilogue ----
    #pragma unroll
    for (int i = 0; i < 4; i++) {
        #pragma unroll
        for (int j = 0; j < 4; j++) {
            int row0 = bm + warp_m * 64 + i * 16 + (lane >> 2);
            int col  = bn + warp_n * 32 + j * 8 + 2 * (lane & 3);
            float2 bv = *(const float2*)(bias + col);
            #pragma unroll
            for (int half = 0; half < 2; half++) {
                int row = row0 + half * 8;
                float rx = acc[i][j][half * 2 + 0] + bv.x;
                float ry = acc[i][j][half * 2 + 1] + bv.y;
                if (epi == 1) {
                    rx = 0.5f * rx * (1.0f + erff(rx * 0.70710678118654752f));
                    ry = 0.5f * ry * (1.0f + erff(ry * 0.70710678118654752f));
                } else if (epi == 2) {
                    float2 rv = *(const float2*)(resid + (size_t)row * N + col);
                    rx += rv.x; ry += rv.y;
                }
                *(float2*)(C + (size_t)row * N + col) = make_float2(rx, ry);
            }
        }
    }
}

// ---------------- causal flash attention (fp32, D=64, D split over lane pair)
// grid: (T/64, NH, B), block 128: thread = (query = tid>>1, half = tid&1)
__global__ __launch_bounds__(128) void attn_kernel(
    const float* __restrict__ Q, const float* __restrict__ K,
    const float* __restrict__ V, float* __restrict__ O)
{
    __shared__ float Ks[64][64];
    __shared__ float Vs[64][64];
    __shared__ float Ss[64][64];   // [j][q]

    const int qt  = blockIdx.x;
    const int h   = blockIdx.y;
    const int b   = blockIdx.z;
    const int tid = threadIdx.x;
    const int q    = tid >> 1;
    const int half = tid & 1;
    const int qglob = qt * 64 + q;
    const unsigned pairmask = 3u << (tid & 30 & 31);  // the two lanes of this pair

    const float* qrow = Q + ((size_t)(b * TT + qglob)) * HH + h * DD + half * 32;

    float qv[32], o[32];
    #pragma unroll
    for (int d4 = 0; d4 < 8; d4++) {
        float4 v = *(const float4*)(qrow + d4 * 4);
        qv[d4*4+0]=v.x; qv[d4*4+1]=v.y; qv[d4*4+2]=v.z; qv[d4*4+3]=v.w;
    }
    #pragma unroll
    for (int d = 0; d < 32; d++) o[d] = 0.f;

    float m = -1e30f, l = 0.f;

    for (int kt = 0; kt <= qt; kt++) {
        __syncthreads();
        for (int idx = tid; idx < 64 * 16; idx += 128) {
            int j  = idx >> 4;
            int c4 = (idx & 15) * 4;
            size_t base = ((size_t)(b * TT + kt * 64 + j)) * HH + h * DD + c4;
            *(float4*)&Ks[j][c4] = *(const float4*)(K + base);
            *(float4*)&Vs[j][c4] = *(const float4*)(V + base);
        }
        __syncthreads();

        const int jmax = (kt == qt) ? (q + 1) : 64;
        float tmax = -1e30f;
        for (int j = 0; j < jmax; j++) {
            float s0 = 0.f, s1 = 0.f, s2 = 0.f, s3 = 0.f;
            #pragma unroll
            for (int d4 = 0; d4 < 8; d4++) {
                float4 kv = *(const float4*)&Ks[j][half * 32 + d4 * 4];
                s0 = fmaf(qv[d4*4+0], kv.x, s0);
                s1 = fmaf(qv[d4*4+1], kv.y, s1);
                s2 = fmaf(qv[d4*4+2], kv.z, s2);
                s3 = fmaf(qv[d4*4+3], kv.w, s3);
            }
            float s = (s0 + s1) + (s2 + s3);
            s += __shfl_xor_sync(pairmask, s, 1);
            s *= 0.125f;                      // 1/sqrt(64)
            if (!half) Ss[j][q] = s;
            tmax = fmaxf(tmax, s);
        }
        __syncwarp();

        float mnew = fmaxf(m, tmax);
        float f = __expf(m - mnew);
        l *= f;
        #pragma unroll
        for (int d = 0; d < 32; d++) o[d] *= f;

        for (int j = 0; j < jmax; j++) {
            float p = __expf(Ss[j][q] - mnew);
            l += p;
            #pragma unroll
            for (int d4 = 0; d4 < 8; d4++) {
                float4 vv = *(const float4*)&Vs[j][half * 32 + d4 * 4];
                o[d4*4+0] = fmaf(p, vv.x, o[d4*4+0]);
                o[d4*4+1] = fmaf(p, vv.y, o[d4*4+1]);
                o[d4*4+2] = fmaf(p, vv.z, o[d4*4+2]);
                o[d4*4+3] = fmaf(p, vv.w, o[d4*4+3]);
            }
        }
        m = mnew;
    }

    const float inv = 1.f / l;
    float* orow = O + ((size_t)(b * TT + qglob)) * HH + h * DD + half * 32;
    #pragma unroll
    for (int d4 = 0; d4 < 8; d4++) {
        *(float4*)(orow + d4 * 4) = make_float4(o[d4*4+0]*inv, o[d4*4+1]*inv,
                                                o[d4*4+2]*inv, o[d4*4+3]*inv);
    }
}

// ---------------- LayerNorm over last dim (1024) ---------------------------
__global__ __launch_bounds__(256) void ln_kernel(
    const float* __restrict__ in, const float* __restrict__ gamma,
    const float* __restrict__ beta, float* __restrict__ out)
{
    __shared__ float red[256];
    const int row = blockIdx.x;
    const int tid = threadIdx.x;
    const float* p = in + (size_t)row * HH;

    float4 v = *(const float4*)(p + tid * 4);
    red[tid] = v.x + v.y + v.z + v.w;
    __syncthreads();
    #pragma unroll
    for (int off = 128; off > 0; off >>= 1) {
        if (tid < off) red[tid] += red[tid + off];
        __syncthreads();
    }
    const float mean = red[0] * (1.0f / HH);
    __syncthreads();

    float dx = v.x - mean, dy = v.y - mean, dz = v.z - mean, dw = v.w - mean;
    red[tid] = dx * dx + dy * dy + dz * dz + dw * dw;
    __syncthreads();
    #pragma unroll
    for (int off = 128; off > 0; off >>= 1) {
        if (tid < off) red[tid] += red[tid + off];
        __syncthreads();
    }
    const float rstd = rsqrtf(red[0] * (1.0f / HH) + 1e-5f);

    float4 g  = *(const float4*)(gamma + tid * 4);
    float4 be = *(const float4*)(beta + tid * 4);
    float4 rr;
    rr.x = dx * rstd * g.x + be.x;
    rr.y = dy * rstd * g.y + be.y;
    rr.z = dz * rstd * g.z + be.z;
    rr.w = dw * rstd * g.w + be.w;
    *(float4*)(out + (size_t)row * HH + tid * 4) = rr;
}

// ---------------- launcher -------------------------------------------------
extern "C" void kernel_launch(void* const* d_in, const int* in_sizes, int n_in,
                              void* d_out, int out_size)
{
    const float* Wq  = (const float*)d_in[1];
    const float* bq  = (const float*)d_in[2];
    const float* Wk  = (const float*)d_in[3];
    const float* bk  = (const float*)d_in[4];
    const float* Wv  = (const float*)d_in[5];
    const float* bv  = (const float*)d_in[6];
    const float* Wp  = (const float*)d_in[7];
    const float* bp  = (const float*)d_in[8];
    const float* W1  = (const float*)d_in[9];
    const float* b1  = (const float*)d_in[10];
    const float* W2  = (const float*)d_in[11];
    const float* b2  = (const float*)d_in[12];
    const float* g1w = (const float*)d_in[13];
    const float* be1 = (const float*)d_in[14];
    const float* g2w = (const float*)d_in[15];
    const float* be2 = (const float*)d_in[16];

    float *gx, *gq, *gk, *gv, *go, *gt, *gh;
    cudaGetSymbolAddress((void**)&gx, g_x);
    cudaGetSymbolAddress((void**)&gq, g_q);
    cudaGetSymbolAddress((void**)&gk, g_k);
    cudaGetSymbolAddress((void**)&gv, g_v);
    cudaGetSymbolAddress((void**)&go, g_o);
    cudaGetSymbolAddress((void**)&gt, g_t);
    cudaGetSymbolAddress((void**)&gh, g_h);

    cudaMemcpyAsync(gx, d_in[0], (size_t)MM * HH * sizeof(float),
                    cudaMemcpyDeviceToDevice, 0);

    const dim3 gridH(HH / BN, MM / BM);    // (8, 32)
    const dim3 gridF(FFF / BN, MM / BM);   // (32, 32)
    const dim3 gridA(TT / 64, NHH, BB);

    for (int l = 0; l < LL; l++) {
        const size_t wo  = (size_t)l * HH * HH;
        const size_t bo  = (size_t)l * HH;
        const size_t w1o = (size_t)l * HH * FFF;
        const size_t b1o = (size_t)l * FFF;
        const size_t w2o = (size_t)l * FFF * HH;

        gemm_kernel<<<gridH, 256>>>(gx, Wq + wo, bq + bo, nullptr, gq, MM, HH, HH, 0);
        gemm_kernel<<<gridH, 256>>>(gx, Wk + wo, bk + bo, nullptr, gk, MM, HH, HH, 0);
        gemm_kernel<<<gridH, 256>>>(gx, Wv + wo, bv + bo, nullptr, gv, MM, HH, HH, 0);

        attn_kernel<<<gridA, 128>>>(gq, gk, gv, go);

        gemm_kernel<<<gridH, 256>>>(go, Wp + wo, bp + bo, gx, gt, MM, HH, HH, 2);
        ln_kernel<<<MM, 256>>>(gt, g1w + bo, be1 + bo, gx);

        gemm_kernel<<<gridF, 256>>>(gx, W1 + w1o, b1 + b1o, nullptr, gh, MM, FFF, HH, 1);
        gemm_kernel<<<gridH, 256>>>(gh, W2 + w2o, b2 + bo, gx, gt, MM, HH, FFF, 2);
        ln_kernel<<<MM, 256>>>(gt, g2w + bo, be2 + bo, gx);
    }

    cudaMemcpyAsync(d_out, gx, (size_t)MM * HH * sizeof(float),
                    cudaMemcpyDeviceToDevice, 0);
}

// round 3
// speedup vs baseline: 1.1501x; 1.0222x over previous
#include <cuda_runtime.h>
#include <cuda_bf16.h>
#include <math.h>
#include <stdint.h>

#define BB 2
#define TT 2048
#define HH 1024
#define NHH 16
#define DD 64
#define FFF 4096
#define LL 6
#define MM (BB*TT)   // 4096 rows
#define H3 (3*HH)

typedef __nv_bfloat16 bf16;

// ---------------- device-global scratch (no allocation) --------------------
__device__ float g_x [MM*HH];
__device__ bf16  g_xh[MM*HH];
__device__ bf16  g_xl[MM*HH];
__device__ float g_qkv[MM*H3];
__device__ bf16  g_oh[MM*HH];
__device__ bf16  g_ol[MM*HH];
__device__ float g_t [MM*HH];
__device__ bf16  g_hh[MM*FFF];
__device__ bf16  g_hl[MM*FFF];
// split+transposed weights [N][K] bf16
__device__ bf16  w_qkv_h[LL*H3*HH],  w_qkv_l[LL*H3*HH];
__device__ bf16  w_p_h  [LL*HH*HH],  w_p_l  [LL*HH*HH];
__device__ bf16  w_1_h  [LL*FFF*HH], w_1_l  [LL*FFF*HH];
__device__ bf16  w_2_h  [LL*HH*FFF], w_2_l  [LL*HH*FFF];
__device__ float g_bqkv[LL*H3];

// ---------------- helpers ---------------------------------------------------
__device__ __forceinline__ void split1(float x, bf16& h, bf16& l) {
    h = __float2bfloat16_rn(x);
    l = __float2bfloat16_rn(x - __bfloat162float(h));
}
__device__ __forceinline__ uint32_t pack2(bf16 a, bf16 b) {
    return (uint32_t)__bfloat16_as_ushort(a) | ((uint32_t)__bfloat16_as_ushort(b) << 16);
}
__device__ __forceinline__ uint32_t smem_u32(const void* p) {
    return (uint32_t)__cvta_generic_to_shared(p);
}
__device__ __forceinline__ void cp16(uint32_t s, const void* g) {
    asm volatile("cp.async.cg.shared.global [%0],[%1],16;\n" :: "r"(s), "l"(g));
}
__device__ __forceinline__ void ldmx4(uint32_t& r0, uint32_t& r1, uint32_t& r2,
                                      uint32_t& r3, uint32_t addr) {
    asm volatile("ldmatrix.sync.aligned.m8n8.x4.shared.b16 {%0,%1,%2,%3},[%4];\n"
                 : "=r"(r0), "=r"(r1), "=r"(r2), "=r"(r3) : "r"(addr));
}
__device__ __forceinline__ void mma16816(float c[4], uint32_t a0, uint32_t a1,
                                         uint32_t a2, uint32_t a3,
                                         uint32_t b0, uint32_t b1) {
    asm volatile(
        "mma.sync.aligned.m16n8k16.row.col.f32.bf16.bf16.f32 "
        "{%0,%1,%2,%3}, {%4,%5,%6,%7}, {%8,%9}, {%0,%1,%2,%3};"
        : "+f"(c[0]), "+f"(c[1]), "+f"(c[2]), "+f"(c[3])
        : "r"(a0), "r"(a1), "r"(a2), "r"(a3), "r"(b0), "r"(b1));
}

// ---------------- weight transpose-split: src[K][N] -> dst[N][K] bf16 hi/lo -
__global__ __launch_bounds__(256) void wsplit_kernel(
    const float* __restrict__ src, bf16* __restrict__ dh, bf16* __restrict__ dl,
    int K, int N, size_t srcStride, size_t dstStride)
{
    __shared__ float t[32][33];
    const float* s = src + blockIdx.z * srcStride;
    const int n0 = blockIdx.x * 32, k0 = blockIdx.y * 32;
    const int tx = threadIdx.x & 31, ty = threadIdx.x >> 5;  // 32x8
    #pragma unroll
    for (int u = 0; u < 4; u++)
        t[ty + u * 8][tx] = s[(size_t)(k0 + ty + u * 8) * N + n0 + tx];
    __syncthreads();
    #pragma unroll
    for (int u = 0; u < 4; u++) {
        float v = t[tx][ty + u * 8];
        bf16 h, l; split1(v, h, l);
        size_t o = blockIdx.z * dstStride + (size_t)(n0 + ty + u * 8) * K + k0 + tx;
        dh[o] = h; dl[o] = l;
    }
}

// ---------------- bias pack + input split ----------------------------------
__global__ void biaspack_kernel(const float* bq, const float* bk, const float* bv) {
    int idx = blockIdx.x * blockDim.x + threadIdx.x;
    if (idx >= LL * H3) return;
    int l = idx / H3, c = idx % H3;
    float v = (c < HH) ? bq[l*HH + c] : (c < 2*HH) ? bk[l*HH + c - HH] : bv[l*HH + c - 2*HH];
    g_bqkv[idx] = v;
}
__global__ void splitx_kernel(const float* __restrict__ in) {
    int id = blockIdx.x * blockDim.x + threadIdx.x;   // 1M float4s
    float4 v = *(const float4*)(in + (size_t)id * 4);
    *(float4*)(g_x + (size_t)id * 4) = v;
    bf16 h0,h1,h2,h3,l0,l1,l2,l3;
    split1(v.x,h0,l0); split1(v.y,h1,l1); split1(v.z,h2,l2); split1(v.w,h3,l3);
    *(uint2*)(g_xh + (size_t)id * 4) = make_uint2(pack2(h0,h1), pack2(h2,h3));
    *(uint2*)(g_xl + (size_t)id * 4) = make_uint2(pack2(l0,l1), pack2(l2,l3));
}

// ---------------- GEMM: C = epi(Asplit * Bsplit + bias [+resid]) -----------
// A hi/lo bf16 [M][K], B hi/lo bf16 [N][K]. epi: 0 bias->f32, 1 bias+gelu->split, 2 bias+resid->f32
#define BM 128
#define BN 128
#define BK 32
#define LDT 40                       // padded bf16 stride per row
#define STAGE_ELE (4*BM*LDT)         // elements per stage (Ah,Al,Bh,Bl)
#define GEMM_SMEM (2*STAGE_ELE*2)    // bytes (2 stages, bf16)

__global__ __launch_bounds__(256) void gemm_kernel(
    const bf16* __restrict__ Agh, const bf16* __restrict__ Agl,
    const bf16* __restrict__ Bgh, const bf16* __restrict__ Bgl,
    const float* __restrict__ bias, const float* __restrict__ resid,
    float* __restrict__ C, bf16* __restrict__ Ch, bf16* __restrict__ Cl,
    int M, int N, int K, int epi)
{
    extern __shared__ __align__(16) bf16 sm[];
    const int tid  = threadIdx.x;
    const int lane = tid & 31;
    const int wid  = tid >> 5;
    const int warp_m = wid & 1;
    const int warp_n = wid >> 1;
    const int bm = blockIdx.y * BM;
    const int bn = blockIdx.x * BN;
    const uint32_t smB = smem_u32(sm);

    float acc[4][4][4];
    #pragma unroll
    for (int i = 0; i < 4; i++)
        #pragma unroll
        for (int j = 0; j < 4; j++)
            #pragma unroll
            for (int u = 0; u < 4; u++) acc[i][j][u] = 0.f;

    // cp.async loader: thread -> row r=tid>>1, 2 chunks of 16B at chunk base
    const int r  = tid >> 1;
    const int cb = (tid & 1) * 16;          // element offset 0 or 16
    const uint32_t soff = (uint32_t)(r * LDT + cb) * 2;

    const int ntiles = K / BK;
    #pragma unroll 1
    for (int pre = 0; pre < 1; pre++) {     // prologue load stage 0
        uint32_t st = smB;
        const size_t ga = (size_t)(bm + r) * K + cb;
        const size_t gb = (size_t)(bn + r) * K + cb;
        cp16(st + soff,                    Agh + ga);
        cp16(st + soff + 16,               Agh + ga + 8);
        cp16(st + BM*LDT*2 + soff,         Agl + ga);
        cp16(st + BM*LDT*2 + soff + 16,    Agl + ga + 8);
        cp16(st + 2*BM*LDT*2 + soff,       Bgh + gb);
        cp16(st + 2*BM*LDT*2 + soff + 16,  Bgh + gb + 8);
        cp16(st + 3*BM*LDT*2 + soff,       Bgl + gb);
        cp16(st + 3*BM*LDT*2 + soff + 16,  Bgl + gb + 8);
    }
    asm volatile("cp.async.commit_group;\n");

    const int lr = lane & 15, lc = lane >> 4;

    for (int kt = 0; kt < ntiles; kt++) {
        if (kt + 1 < ntiles) {
            uint32_t st = smB + ((kt + 1) & 1) * (STAGE_ELE * 2);
            const int k0 = (kt + 1) * BK;
            const size_t ga = (size_t)(bm + r) * K + k0 + cb;
            const size_t gb = (size_t)(bn + r) * K + k0 + cb;
            cp16(st + soff,                    Agh + ga);
            cp16(st + soff + 16,               Agh + ga + 8);
            cp16(st + BM*LDT*2 + soff,         Agl + ga);
            cp16(st + BM*LDT*2 + soff + 16,    Agl + ga + 8);
            cp16(st + 2*BM*LDT*2 + soff,       Bgh + gb);
            cp16(st + 2*BM*LDT*2 + soff + 16,  Bgh + gb + 8);
            cp16(st + 3*BM*LDT*2 + soff,       Bgl + gb);
            cp16(st + 3*BM*LDT*2 + soff + 16,  Bgl + gb + 8);
        }
        asm volatile("cp.async.commit_group;\n");
        asm volatile("cp.async.wait_group 1;\n");
        __syncthreads();

        const uint32_t st = smB + (kt & 1) * (STAGE_ELE * 2);
        const uint32_t Ah = st;
        const uint32_t Al = st + BM*LDT*2;
        const uint32_t Bh = st + 2*BM*LDT*2;
        const uint32_t Bl = st + 3*BM*LDT*2;

        #pragma unroll
        for (int kk = 0; kk < 2; kk++) {
            const uint32_t coff = (uint32_t)(kk * 16 + lc * 8) * 2;
            uint32_t ah[4][4], alr[4][4], bh[4][2], bl[4][2];
            #pragma unroll
            for (int i = 0; i < 4; i++) {
                uint32_t ra = (uint32_t)((warp_m*64 + i*16 + lr) * LDT) * 2 + coff;
                ldmx4(ah[i][0], ah[i][1], ah[i][2], ah[i][3], Ah + ra);
                ldmx4(alr[i][0], alr[i][1], alr[i][2], alr[i][3], Al + ra);
            }
            #pragma unroll
            for (int j16 = 0; j16 < 2; j16++) {
                uint32_t rb = (uint32_t)((warp_n*32 + j16*16 + lr) * LDT) * 2 + coff;
                uint32_t r0, r1, r2, r3;
                ldmx4(r0, r1, r2, r3, Bh + rb);
                bh[j16*2][0] = r0; bh[j16*2][1] = r2;
                bh[j16*2+1][0] = r1; bh[j16*2+1][1] = r3;
                ldmx4(r0, r1, r2, r3, Bl + rb);
                bl[j16*2][0] = r0; bl[j16*2][1] = r2;
                bl[j16*2+1][0] = r1; bl[j16*2+1][1] = r3;
            }
            #pragma unroll
            for (int i = 0; i < 4; i++)
                #pragma unroll
                for (int j = 0; j < 4; j++)
                    mma16816(acc[i][j], ah[i][0],ah[i][1],ah[i][2],ah[i][3], bh[j][0],bh[j][1]);
            #pragma unroll
            for (int i = 0; i < 4; i++)
                #pragma unroll
                for (int j = 0; j < 4; j++)
                    mma16816(acc[i][j], ah[i][0],ah[i][1],ah[i][2],ah[i][3], bl[j][0],bl[j][1]);
            #pragma unroll
            for (int i = 0; i < 4; i++)
                #pragma unroll
                for (int j = 0; j < 4; j++)
                    mma16816(acc[i][j], alr[i][0],alr[i][1],alr[i][2],alr[i][3], bh[j][0],bh[j][1]);
        }
        __syncthreads();
    }

    // epilogue
    #pragma unroll
    for (int i = 0; i < 4; i++) {
        #pragma unroll
        for (int j = 0; j < 4; j++) {
            const int row0 = bm + warp_m*64 + i*16 + (lane >> 2);
            const int col  = bn + warp_n*32 + j*8 + 2*(lane & 3);
            const float2 bv = *(const float2*)(bias + col);
            #pragma unroll
            for (int half = 0; half < 2; half++) {
                const int row = row0 + half * 8;
                float rx = acc[i][j][half*2+0] + bv.x;
                float ry = acc[i][j][half*2+1] + bv.y;
                if (epi == 1) {
                    rx = 0.5f * rx * (1.0f + erff(rx * 0.70710678118654752f));
                    ry = 0.5f * ry * (1.0f + erff(ry * 0.70710678118654752f));
                    bf16 hx,lx,hy,ly;
                    split1(rx,hx,lx); split1(ry,hy,ly);
                    *(uint32_t*)(Ch + (size_t)row*N + col) = pack2(hx,hy);
                    *(uint32_t*)(Cl + (size_t)row*N + col) = pack2(lx,ly);
                } else if (epi == 2) {
                    const float2 rv = *(const float2*)(resid + (size_t)row*N + col);
                    *(float2*)(C + (size_t)row*N + col) = make_float2(rx + rv.x, ry + rv.y);
                } else {
                    *(float2*)(C + (size_t)row*N + col) = make_float2(rx, ry);
                }
            }
        }
    }
}

// ---------------- causal flash attention (fp32, D split over lane pair) -----
// qkv layout [M][3H]; writes o split (bf16 hi/lo)
__global__ __launch_bounds__(128) void attn_kernel(const float* __restrict__ QKV)
{
    __shared__ float Ks[64][64];
    __shared__ float Vs[64][64];
    __shared__ float Ss[64][64];

    const int qt  = blockIdx.x;
    const int h   = blockIdx.y;
    const int b   = blockIdx.z;
    const int tid = threadIdx.x;
    const int q    = tid >> 1;
    const int half = tid & 1;
    const int qglob = qt * 64 + q;
    const unsigned pairmask = 3u << (tid & 30 & 31);

    const float* qrow = QKV + ((size_t)(b*TT + qglob)) * H3 + h*DD + half*32;

    float qv[32], o[32];
    #pragma unroll
    for (int d4 = 0; d4 < 8; d4++) {
        float4 v = *(const float4*)(qrow + d4*4);
        qv[d4*4+0]=v.x; qv[d4*4+1]=v.y; qv[d4*4+2]=v.z; qv[d4*4+3]=v.w;
    }
    #pragma unroll
    for (int d = 0; d < 32; d++) o[d] = 0.f;

    float m = -1e30f, l = 0.f;

    for (int kt = 0; kt <= qt; kt++) {
        __syncthreads();
        for (int idx = tid; idx < 64*16; idx += 128) {
            int j  = idx >> 4;
            int c4 = (idx & 15) * 4;
            size_t base = ((size_t)(b*TT + kt*64 + j)) * H3 + h*DD + c4;
            *(float4*)&Ks[j][c4] = *(const float4*)(QKV + base + HH);
            *(float4*)&Vs[j][c4] = *(const float4*)(QKV + base + 2*HH);
        }
        __syncthreads();

        const int jmax = (kt == qt) ? (q + 1) : 64;
        float tmax = -1e30f;
        for (int j = 0; j < jmax; j++) {
            float s0=0.f, s1=0.f, s2=0.f, s3=0.f;
            #pragma unroll
            for (int d4 = 0; d4 < 8; d4++) {
                float4 kv = *(const float4*)&Ks[j][half*32 + d4*4];
                s0 = fmaf(qv[d4*4+0], kv.x, s0);
                s1 = fmaf(qv[d4*4+1], kv.y, s1);
                s2 = fmaf(qv[d4*4+2], kv.z, s2);
                s3 = fmaf(qv[d4*4+3], kv.w, s3);
            }
            float s = (s0+s1) + (s2+s3);
            s += __shfl_xor_sync(pairmask, s, 1);
            s *= 0.125f;
            if (!half) Ss[j][q] = s;
            tmax = fmaxf(tmax, s);
        }
        __syncwarp();

        float mnew = fmaxf(m, tmax);
        float f = __expf(m - mnew);
        l *= f;
        #pragma unroll
        for (int d = 0; d < 32; d++) o[d] *= f;

        for (int j = 0; j < jmax; j++) {
            float p = __expf(Ss[j][q] - mnew);
            l += p;
            #pragma unroll
            for (int d4 = 0; d4 < 8; d4++) {
                float4 vv = *(const float4*)&Vs[j][half*32 + d4*4];
                o[d4*4+0] = fmaf(p, vv.x, o[d4*4+0]);
                o[d4*4+1] = fmaf(p, vv.y, o[d4*4+1]);
                o[d4*4+2] = fmaf(p, vv.z, o[d4*4+2]);
                o[d4*4+3] = fmaf(p, vv.w, o[d4*4+3]);
            }
        }
        m = mnew;
    }

    const float inv = 1.f / l;
    const size_t ob = ((size_t)(b*TT + qglob)) * HH + h*DD + half*32;
    #pragma unroll
    for (int d4 = 0; d4 < 8; d4++) {
        float e0 = o[d4*4+0]*inv, e1 = o[d4*4+1]*inv, e2 = o[d4*4+2]*inv, e3 = o[d4*4+3]*inv;
        bf16 h0,h1,h2,h3,l0,l1,l2,l3;
        split1(e0,h0,l0); split1(e1,h1,l1); split1(e2,h2,l2); split1(e3,h3,l3);
        *(uint2*)(g_oh + ob + d4*4) = make_uint2(pack2(h0,h1), pack2(h2,h3));
        *(uint2*)(g_ol + ob + d4*4) = make_uint2(pack2(l0,l1), pack2(l2,l3));
    }
}

// ---------------- LayerNorm: fp32 out + bf16 split out ---------------------
__global__ __launch_bounds__(256) void ln_kernel(
    const float* __restrict__ in, const float* __restrict__ gamma,
    const float* __restrict__ beta, float* __restrict__ out,
    bf16* __restrict__ outh, bf16* __restrict__ outl)
{
    __shared__ float red[256];
    const int row = blockIdx.x;
    const int tid = threadIdx.x;
    const float* p = in + (size_t)row * HH;

    float4 v = *(const float4*)(p + tid * 4);
    red[tid] = v.x + v.y + v.z + v.w;
    __syncthreads();
    #pragma unroll
    for (int off = 128; off > 0; off >>= 1) {
        if (tid < off) red[tid] += red[tid + off];
        __syncthreads();
    }
    const float mean = red[0] * (1.0f / HH);
    __syncthreads();

    float dx = v.x-mean, dy = v.y-mean, dz = v.z-mean, dw = v.w-mean;
    red[tid] = dx*dx + dy*dy + dz*dz + dw*dw;
    __syncthreads();
    #pragma unroll
    for (int off = 128; off > 0; off >>= 1) {
        if (tid < off) red[tid] += red[tid + off];
        __syncthreads();
    }
    const float rstd = rsqrtf(red[0] * (1.0f / HH) + 1e-5f);

    float4 g  = *(const float4*)(gamma + tid * 4);
    float4 be = *(const float4*)(beta + tid * 4);
    float4 rr;
    rr.x = dx*rstd*g.x + be.x;
    rr.y = dy*rstd*g.y + be.y;
    rr.z = dz*rstd*g.z + be.z;
    rr.w = dw*rstd*g.w + be.w;
    *(float4*)(out + (size_t)row*HH + tid*4) = rr;

    bf16 h0,h1,h2,h3,l0,l1,l2,l3;
    split1(rr.x,h0,l0); split1(rr.y,h1,l1); split1(rr.z,h2,l2); split1(rr.w,h3,l3);
    *(uint2*)(outh + (size_t)row*HH + tid*4) = make_uint2(pack2(h0,h1), pack2(h2,h3));
    *(uint2*)(outl + (size_t)row*HH + tid*4) = make_uint2(pack2(l0,l1), pack2(l2,l3));
}

// ---------------- launcher -------------------------------------------------
extern "C" void kernel_launch(void* const* d_in, const int* in_sizes, int n_in,
                              void* d_out, int out_size)
{
    const float* Wq  = (const float*)d_in[1];
    const float* bq  = (const float*)d_in[2];
    const float* Wk  = (const float*)d_in[3];
    const float* bk  = (const float*)d_in[4];
    const float* Wv  = (const float*)d_in[5];
    const float* bv  = (const float*)d_in[6];
    const float* Wp  = (const float*)d_in[7];
    const float* bp  = (const float*)d_in[8];
    const float* W1  = (const float*)d_in[9];
    const float* b1  = (const float*)d_in[10];
    const float* W2  = (const float*)d_in[11];
    const float* b2  = (const float*)d_in[12];
    const float* g1w = (const float*)d_in[13];
    const float* be1 = (const float*)d_in[14];
    const float* g2w = (const float*)d_in[15];
    const float* be2 = (const float*)d_in[16];

    cudaFuncSetAttribute(gemm_kernel, cudaFuncAttributeMaxDynamicSharedMemorySize, GEMM_SMEM);

    float *gx, *gqkv, *gt, *gbqkv;
    bf16 *gxh, *gxl, *goh, *gol, *ghh, *ghl;
    bf16 *wqh, *wql, *wph, *wpl, *w1h, *w1l, *w2h, *w2l;
    cudaGetSymbolAddress((void**)&gx,   g_x);
    cudaGetSymbolAddress((void**)&gxh,  g_xh);
    cudaGetSymbolAddress((void**)&gxl,  g_xl);
    cudaGetSymbolAddress((void**)&gqkv, g_qkv);
    cudaGetSymbolAddress((void**)&goh,  g_oh);
    cudaGetSymbolAddress((void**)&gol,  g_ol);
    cudaGetSymbolAddress((void**)&gt,   g_t);
    cudaGetSymbolAddress((void**)&ghh,  g_hh);
    cudaGetSymbolAddress((void**)&ghl,  g_hl);
    cudaGetSymbolAddress((void**)&wqh,  w_qkv_h);
    cudaGetSymbolAddress((void**)&wql,  w_qkv_l);
    cudaGetSymbolAddress((void**)&wph,  w_p_h);
    cudaGetSymbolAddress((void**)&wpl,  w_p_l);
    cudaGetSymbolAddress((void**)&w1h,  w_1_h);
    cudaGetSymbolAddress((void**)&w1l,  w_1_l);
    cudaGetSymbolAddress((void**)&w2h,  w_2_h);
    cudaGetSymbolAddress((void**)&w2l,  w_2_l);
    cudaGetSymbolAddress((void**)&gbqkv, g_bqkv);

    // ---- preprocessing: weight transpose+split, bias pack, x split ----
    const dim3 tb(256);
    wsplit_kernel<<<dim3(HH/32, HH/32, LL), tb>>>(Wq, wqh,          wql,          HH, HH, (size_t)HH*HH, (size_t)H3*HH);
    wsplit_kernel<<<dim3(HH/32, HH/32, LL), tb>>>(Wk, wqh + HH*HH,  wql + HH*HH,  HH, HH, (size_t)HH*HH, (size_t)H3*HH);
    wsplit_kernel<<<dim3(HH/32, HH/32, LL), tb>>>(Wv, wqh + 2*HH*HH,wql + 2*HH*HH,HH, HH, (size_t)HH*HH, (size_t)H3*HH);
    wsplit_kernel<<<dim3(HH/32, HH/32, LL), tb>>>(Wp, wph, wpl, HH, HH, (size_t)HH*HH, (size_t)HH*HH);
    wsplit_kernel<<<dim3(FFF/32, HH/32, LL), tb>>>(W1, w1h, w1l, HH, FFF, (size_t)HH*FFF, (size_t)FFF*HH);
    wsplit_kernel<<<dim3(HH/32, FFF/32, LL), tb>>>(W2, w2h, w2l, FFF, HH, (size_t)FFF*HH, (size_t)HH*FFF);
    biaspack_kernel<<<(LL*H3 + 255)/256, 256>>>(bq, bk, bv);
    splitx_kernel<<<MM*HH/1024, 256>>>((const float*)d_in[0]);

    const dim3 gridQKV(H3/BN, MM/BM);    // (24, 32)
    const dim3 gridH(HH/BN, MM/BM);      // (8, 32)
    const dim3 gridF(FFF/BN, MM/BM);     // (32, 32)
    const dim3 gridA(TT/64, NHH, BB);

    for (int l = 0; l < LL; l++) {
        const size_t bo  = (size_t)l * HH;

        // fused QKV projection -> g_qkv fp32
        gemm_kernel<<<gridQKV, 256, GEMM_SMEM>>>(
            gxh, gxl, wqh + (size_t)l*H3*HH, wql + (size_t)l*H3*HH,
            gbqkv + (size_t)l*H3, nullptr, gqkv, nullptr, nullptr,
            MM, H3, HH, 0);

        // attention -> o split
        attn_kernel<<<gridA, 128>>>(gqkv);

        // output projection + residual -> t fp32 ; LN1 -> x fp32 + split
        gemm_kernel<<<gridH, 256, GEMM_SMEM>>>(
            goh, gol, wph + (size_t)l*HH*HH, wpl + (size_t)l*HH*HH,
            bp + bo, gx, gt, nullptr, nullptr, MM, HH, HH, 2);
        ln_kernel<<<MM, 256>>>(gt, g1w + bo, be1 + bo, gx, gxh, gxl);

        // MLP
        gemm_kernel<<<gridF, 256, GEMM_SMEM>>>(
            gxh, gxl, w1h + (size_t)l*FFF*HH, w1l + (size_t)l*FFF*HH,
            b1 + (size_t)l*FFF, nullptr, nullptr, ghh, ghl, MM, FFF, HH, 1);
        gemm_kernel<<<gridH, 256, GEMM_SMEM>>>(
            ghh, ghl, w2h + (size_t)l*HH*FFF, w2l + (size_t)l*HH*FFF,
            b2 + bo, gx, gt, nullptr, nullptr, MM, HH, FFF, 2);
        ln_kernel<<<MM, 256>>>(gt, g2w + bo, be2 + bo, gx, gxh, gxl);
    }

    cudaMemcpyAsync(d_out, gx, (size_t)MM*HH*sizeof(float),
                    cudaMemcpyDeviceToDevice, 0);
}

// round 4
// speedup vs baseline: 2.1758x; 1.8918x over previous
#include <cuda_runtime.h>
#include <cuda_bf16.h>
#include <math.h>
#include <stdint.h>

#define BB 2
#define TT 2048
#define HH 1024
#define NHH 16
#define DD 64
#define FFF 4096
#define LL 6
#define MM (BB*TT)
#define H3 (3*HH)

typedef __nv_bfloat16 bf16;

// ---------------- device-global scratch ------------------------------------
__device__ float g_x [MM*HH];
__device__ bf16  g_xh[MM*HH];
__device__ bf16  g_xl[MM*HH];
__device__ bf16  g_qkvh[MM*H3];
__device__ bf16  g_qkvl[MM*H3];
__device__ bf16  g_oh[MM*HH];
__device__ bf16  g_ol[MM*HH];
__device__ float g_t [MM*HH];
__device__ bf16  g_hh[MM*FFF];
__device__ bf16  g_hl[MM*FFF];
__device__ bf16  w_qkv_h[LL*H3*HH],  w_qkv_l[LL*H3*HH];
__device__ bf16  w_p_h  [LL*HH*HH],  w_p_l  [LL*HH*HH];
__device__ bf16  w_1_h  [LL*FFF*HH], w_1_l  [LL*FFF*HH];
__device__ bf16  w_2_h  [LL*HH*FFF], w_2_l  [LL*HH*FFF];
__device__ float g_bqkv[LL*H3];

// ---------------- helpers ---------------------------------------------------
__device__ __forceinline__ void split1(float x, bf16& h, bf16& l) {
    h = __float2bfloat16_rn(x);
    l = __float2bfloat16_rn(x - __bfloat162float(h));
}
__device__ __forceinline__ uint32_t pack2(bf16 a, bf16 b) {
    return (uint32_t)__bfloat16_as_ushort(a) | ((uint32_t)__bfloat16_as_ushort(b) << 16);
}
__device__ __forceinline__ uint32_t smem_u32(const void* p) {
    return (uint32_t)__cvta_generic_to_shared(p);
}
__device__ __forceinline__ void cp16(uint32_t s, const void* g) {
    asm volatile("cp.async.cg.shared.global [%0],[%1],16;\n" :: "r"(s), "l"(g));
}
__device__ __forceinline__ void ldmx4(uint32_t& r0, uint32_t& r1, uint32_t& r2,
                                      uint32_t& r3, uint32_t addr) {
    asm volatile("ldmatrix.sync.aligned.m8n8.x4.shared.b16 {%0,%1,%2,%3},[%4];\n"
                 : "=r"(r0), "=r"(r1), "=r"(r2), "=r"(r3) : "r"(addr));
}
__device__ __forceinline__ void ldmx4t(uint32_t& r0, uint32_t& r1, uint32_t& r2,
                                       uint32_t& r3, uint32_t addr) {
    asm volatile("ldmatrix.sync.aligned.m8n8.x4.trans.shared.b16 {%0,%1,%2,%3},[%4];\n"
                 : "=r"(r0), "=r"(r1), "=r"(r2), "=r"(r3) : "r"(addr));
}
__device__ __forceinline__ void mma16816(float c[4], uint32_t a0, uint32_t a1,
                                         uint32_t a2, uint32_t a3,
                                         uint32_t b0, uint32_t b1) {
    asm volatile(
        "mma.sync.aligned.m16n8k16.row.col.f32.bf16.bf16.f32 "
        "{%0,%1,%2,%3}, {%4,%5,%6,%7}, {%8,%9}, {%0,%1,%2,%3};"
        : "+f"(c[0]), "+f"(c[1]), "+f"(c[2]), "+f"(c[3])
        : "r"(a0), "r"(a1), "r"(a2), "r"(a3), "r"(b0), "r"(b1));
}

// ---------------- weight transpose-split: src[K][N] -> dst[N][K] bf16 hi/lo -
__global__ __launch_bounds__(256) void wsplit_kernel(
    const float* __restrict__ src, bf16* __restrict__ dh, bf16* __restrict__ dl,
    int K, int N, size_t srcStride, size_t dstStride)
{
    __shared__ float t[32][33];
    const float* s = src + blockIdx.z * srcStride;
    const int n0 = blockIdx.x * 32, k0 = blockIdx.y * 32;
    const int tx = threadIdx.x & 31, ty = threadIdx.x >> 5;
    #pragma unroll
    for (int u = 0; u < 4; u++)
        t[ty + u * 8][tx] = s[(size_t)(k0 + ty + u * 8) * N + n0 + tx];
    __syncthreads();
    #pragma unroll
    for (int u = 0; u < 4; u++) {
        float v = t[tx][ty + u * 8];
        bf16 h, l; split1(v, h, l);
        size_t o = blockIdx.z * dstStride + (size_t)(n0 + ty + u * 8) * K + k0 + tx;
        dh[o] = h; dl[o] = l;
    }
}

__global__ void biaspack_kernel(const float* bq, const float* bk, const float* bv) {
    int idx = blockIdx.x * blockDim.x + threadIdx.x;
    if (idx >= LL * H3) return;
    int l = idx / H3, c = idx % H3;
    float v = (c < HH) ? bq[l*HH + c] : (c < 2*HH) ? bk[l*HH + c - HH] : bv[l*HH + c - 2*HH];
    g_bqkv[idx] = v;
}
__global__ void splitx_kernel(const float* __restrict__ in) {
    int id = blockIdx.x * blockDim.x + threadIdx.x;
    float4 v = *(const float4*)(in + (size_t)id * 4);
    *(float4*)(g_x + (size_t)id * 4) = v;
    bf16 h0,h1,h2,h3,l0,l1,l2,l3;
    split1(v.x,h0,l0); split1(v.y,h1,l1); split1(v.z,h2,l2); split1(v.w,h3,l3);
    *(uint2*)(g_xh + (size_t)id * 4) = make_uint2(pack2(h0,h1), pack2(h2,h3));
    *(uint2*)(g_xl + (size_t)id * 4) = make_uint2(pack2(l0,l1), pack2(l2,l3));
}

// ---------------- GEMM ------------------------------------------------------
// epi: 0 bias->f32, 1 bias+gelu->split, 2 bias+resid->f32, 3 bias->split
#define BM 128
#define BN 128
#define BK 32
#define LDT 40
#define STAGE_ELE (4*BM*LDT)
#define GEMM_SMEM (2*STAGE_ELE*2)

__global__ __launch_bounds__(256, 2) void gemm_kernel(
    const bf16* __restrict__ Agh, const bf16* __restrict__ Agl,
    const bf16* __restrict__ Bgh, const bf16* __restrict__ Bgl,
    const float* __restrict__ bias, const float* __restrict__ resid,
    float* __restrict__ C, bf16* __restrict__ Ch, bf16* __restrict__ Cl,
    int M, int N, int K, int epi)
{
    extern __shared__ __align__(16) bf16 sm[];
    const int tid  = threadIdx.x;
    const int lane = tid & 31;
    const int wid  = tid >> 5;
    const int warp_m = wid & 1;
    const int warp_n = wid >> 1;
    const int bm = blockIdx.y * BM;
    const int bn = blockIdx.x * BN;
    const uint32_t smB = smem_u32(sm);

    float acc[4][4][4];
    #pragma unroll
    for (int i = 0; i < 4; i++)
        #pragma unroll
        for (int j = 0; j < 4; j++)
            #pragma unroll
            for (int u = 0; u < 4; u++) acc[i][j][u] = 0.f;

    const int r  = tid >> 1;
    const int cb = (tid & 1) * 16;
    const uint32_t soff = (uint32_t)(r * LDT + cb) * 2;

    const int ntiles = K / BK;
    {
        uint32_t st = smB;
        const size_t ga = (size_t)(bm + r) * K + cb;
        const size_t gb = (size_t)(bn + r) * K + cb;
        cp16(st + soff,                    Agh + ga);
        cp16(st + soff + 16,               Agh + ga + 8);
        cp16(st + BM*LDT*2 + soff,         Agl + ga);
        cp16(st + BM*LDT*2 + soff + 16,    Agl + ga + 8);
        cp16(st + 2*BM*LDT*2 + soff,       Bgh + gb);
        cp16(st + 2*BM*LDT*2 + soff + 16,  Bgh + gb + 8);
        cp16(st + 3*BM*LDT*2 + soff,       Bgl + gb);
        cp16(st + 3*BM*LDT*2 + soff + 16,  Bgl + gb + 8);
    }
    asm volatile("cp.async.commit_group;\n");

    const int lr = lane & 15, lc = lane >> 4;

    for (int kt = 0; kt < ntiles; kt++) {
        if (kt + 1 < ntiles) {
            uint32_t st = smB + ((kt + 1) & 1) * (STAGE_ELE * 2);
            const int k0 = (kt + 1) * BK;
            const size_t ga = (size_t)(bm + r) * K + k0 + cb;
            const size_t gb = (size_t)(bn + r) * K + k0 + cb;
            cp16(st + soff,                    Agh + ga);
            cp16(st + soff + 16,               Agh + ga + 8);
            cp16(st + BM*LDT*2 + soff,         Agl + ga);
            cp16(st + BM*LDT*2 + soff + 16,    Agl + ga + 8);
            cp16(st + 2*BM*LDT*2 + soff,       Bgh + gb);
            cp16(st + 2*BM*LDT*2 + soff + 16,  Bgh + gb + 8);
            cp16(st + 3*BM*LDT*2 + soff,       Bgl + gb);
            cp16(st + 3*BM*LDT*2 + soff + 16,  Bgl + gb + 8);
        }
        asm volatile("cp.async.commit_group;\n");
        asm volatile("cp.async.wait_group 1;\n");
        __syncthreads();

        const uint32_t st = smB + (kt & 1) * (STAGE_ELE * 2);
        const uint32_t Ah = st;
        const uint32_t Al = st + BM*LDT*2;
        const uint32_t Bh = st + 2*BM*LDT*2;
        const uint32_t Bl = st + 3*BM*LDT*2;

        #pragma unroll
        for (int kk = 0; kk < 2; kk++) {
            const uint32_t coff = (uint32_t)(kk * 16 + lc * 8) * 2;
            uint32_t a[4][4], bh[4][2];
            // A-hi frags
            #pragma unroll
            for (int i = 0; i < 4; i++) {
                uint32_t ra = (uint32_t)((warp_m*64 + i*16 + lr) * LDT) * 2 + coff;
                ldmx4(a[i][0], a[i][1], a[i][2], a[i][3], Ah + ra);
            }
            // B-hi frags
            #pragma unroll
            for (int j16 = 0; j16 < 2; j16++) {
                uint32_t rb = (uint32_t)((warp_n*32 + j16*16 + lr) * LDT) * 2 + coff;
                uint32_t r0, r1, r2, r3;
                ldmx4(r0, r1, r2, r3, Bh + rb);
                bh[j16*2][0] = r0; bh[j16*2][1] = r2;
                bh[j16*2+1][0] = r1; bh[j16*2+1][1] = r3;
            }
            // term1: Ahi*Bhi
            #pragma unroll
            for (int i = 0; i < 4; i++)
                #pragma unroll
                for (int j = 0; j < 4; j++)
                    mma16816(acc[i][j], a[i][0],a[i][1],a[i][2],a[i][3], bh[j][0],bh[j][1]);
            // term2: Ahi*Blo
            {
                uint32_t bl[4][2];
                #pragma unroll
                for (int j16 = 0; j16 < 2; j16++) {
                    uint32_t rb = (uint32_t)((warp_n*32 + j16*16 + lr) * LDT) * 2 + coff;
                    uint32_t r0, r1, r2, r3;
                    ldmx4(r0, r1, r2, r3, Bl + rb);
                    bl[j16*2][0] = r0; bl[j16*2][1] = r2;
                    bl[j16*2+1][0] = r1; bl[j16*2+1][1] = r3;
                }
                #pragma unroll
                for (int i = 0; i < 4; i++)
                    #pragma unroll
                    for (int j = 0; j < 4; j++)
                        mma16816(acc[i][j], a[i][0],a[i][1],a[i][2],a[i][3], bl[j][0],bl[j][1]);
            }
            // term3: Alo*Bhi (overwrite dead A-hi regs)
            #pragma unroll
            for (int i = 0; i < 4; i++) {
                uint32_t ra = (uint32_t)((warp_m*64 + i*16 + lr) * LDT) * 2 + coff;
                ldmx4(a[i][0], a[i][1], a[i][2], a[i][3], Al + ra);
            }
            #pragma unroll
            for (int i = 0; i < 4; i++)
                #pragma unroll
                for (int j = 0; j < 4; j++)
                    mma16816(acc[i][j], a[i][0],a[i][1],a[i][2],a[i][3], bh[j][0],bh[j][1]);
        }
        __syncthreads();
    }

    #pragma unroll
    for (int i = 0; i < 4; i++) {
        #pragma unroll
        for (int j = 0; j < 4; j++) {
            const int row0 = bm + warp_m*64 + i*16 + (lane >> 2);
            const int col  = bn + warp_n*32 + j*8 + 2*(lane & 3);
            const float2 bv = *(const float2*)(bias + col);
            #pragma unroll
            for (int half = 0; half < 2; half++) {
                const int row = row0 + half * 8;
                float rx = acc[i][j][half*2+0] + bv.x;
                float ry = acc[i][j][half*2+1] + bv.y;
                if (epi == 1) {
                    rx = 0.5f * rx * (1.0f + erff(rx * 0.70710678118654752f));
                    ry = 0.5f * ry * (1.0f + erff(ry * 0.70710678118654752f));
                }
                if (epi == 1 || epi == 3) {
                    bf16 hx,lx,hy,ly;
                    split1(rx,hx,lx); split1(ry,hy,ly);
                    *(uint32_t*)(Ch + (size_t)row*N + col) = pack2(hx,hy);
                    *(uint32_t*)(Cl + (size_t)row*N + col) = pack2(lx,ly);
                } else if (epi == 2) {
                    const float2 rv = *(const float2*)(resid + (size_t)row*N + col);
                    *(float2*)(C + (size_t)row*N + col) = make_float2(rx + rv.x, ry + rv.y);
                } else {
                    *(float2*)(C + (size_t)row*N + col) = make_float2(rx, ry);
                }
            }
        }
    }
}

// ---------------- tensor-core causal flash attention ------------------------
// 64q x 64k tile per block, 4 warps (16 q each). hi/lo split MMAs, fp32 softmax.
#define AT_LDT 72
#define AT_TILE (64*AT_LDT)                // elements per smem tile
#define ATT_SMEM (6*AT_TILE*2)             // Qh Ql Kh Kl Vh Vl

__global__ __launch_bounds__(128, 4) void attn_kernel(
    const bf16* __restrict__ QKVh, const bf16* __restrict__ QKVl)
{
    extern __shared__ __align__(16) bf16 asmem[];
    const uint32_t sQh = smem_u32(asmem);
    const uint32_t sQl = sQh + AT_TILE*2;
    const uint32_t sKh = sQh + 2*AT_TILE*2;
    const uint32_t sKl = sQh + 3*AT_TILE*2;
    const uint32_t sVh = sQh + 4*AT_TILE*2;
    const uint32_t sVl = sQh + 5*AT_TILE*2;

    const int qt  = blockIdx.x;
    const int h   = blockIdx.y;
    const int b   = blockIdx.z;
    const int tid = threadIdx.x;
    const int w    = tid >> 5;
    const int lane = tid & 31;
    const int lr = lane & 15, lc = lane >> 4;
    const int rr = lane >> 2, cq = lane & 3;

    // load Q tile (hi+lo)
    #pragma unroll
    for (int c = tid; c < 512; c += 128) {
        int row = c >> 3, seg = c & 7;
        size_t g = ((size_t)(b*TT + qt*64 + row))*H3 + h*DD + seg*8;
        uint32_t s = (uint32_t)(row*AT_LDT + seg*8)*2;
        cp16(sQh + s, QKVh + g);
        cp16(sQl + s, QKVl + g);
    }
    asm volatile("cp.async.commit_group;\n");

    float O[8][4];
    #pragma unroll
    for (int j = 0; j < 8; j++)
        #pragma unroll
        for (int u = 0; u < 4; u++) O[j][u] = 0.f;
    float m0 = -1e30f, m1 = -1e30f, l0 = 0.f, l1 = 0.f;

    for (int kt = 0; kt <= qt; kt++) {
        #pragma unroll
        for (int c = tid; c < 512; c += 128) {
            int row = c >> 3, seg = c & 7;
            size_t gk = ((size_t)(b*TT + kt*64 + row))*H3 + HH + h*DD + seg*8;
            uint32_t s = (uint32_t)(row*AT_LDT + seg*8)*2;
            cp16(sKh + s, QKVh + gk);
            cp16(sKl + s, QKVl + gk);
            cp16(sVh + s, QKVh + gk + HH);
            cp16(sVl + s, QKVl + gk + HH);
        }
        asm volatile("cp.async.commit_group;\n");
        asm volatile("cp.async.wait_group 0;\n");
        __syncthreads();

        // ---- S = Q K^T (3-term split) ----
        float S[8][4];
        #pragma unroll
        for (int j = 0; j < 8; j++)
            #pragma unroll
            for (int u = 0; u < 4; u++) S[j][u] = 0.f;

        #pragma unroll
        for (int ks = 0; ks < 4; ks++) {
            const uint32_t coff = (uint32_t)(ks*16 + lc*8)*2;
            uint32_t qh[4], ql[4];
            uint32_t ra = (uint32_t)((w*16 + lr)*AT_LDT)*2 + coff;
            ldmx4(qh[0], qh[1], qh[2], qh[3], sQh + ra);
            ldmx4(ql[0], ql[1], ql[2], ql[3], sQl + ra);
            #pragma unroll
            for (int j16 = 0; j16 < 4; j16++) {
                uint32_t rb = (uint32_t)((j16*16 + lr)*AT_LDT)*2 + coff;
                uint32_t k0,k1,k2,k3;
                ldmx4(k0,k1,k2,k3, sKh + rb);
                mma16816(S[j16*2],   qh[0],qh[1],qh[2],qh[3], k0,k2);
                mma16816(S[j16*2+1], qh[0],qh[1],qh[2],qh[3], k1,k3);
                mma16816(S[j16*2],   ql[0],ql[1],ql[2],ql[3], k0,k2);
                mma16816(S[j16*2+1], ql[0],ql[1],ql[2],ql[3], k1,k3);
                ldmx4(k0,k1,k2,k3, sKl + rb);
                mma16816(S[j16*2],   qh[0],qh[1],qh[2],qh[3], k0,k2);
                mma16816(S[j16*2+1], qh[0],qh[1],qh[2],qh[3], k1,k3);
            }
        }

        // scale + causal mask (diagonal tile)
        #pragma unroll
        for (int j = 0; j < 8; j++)
            #pragma unroll
            for (int u = 0; u < 4; u++) S[j][u] *= 0.125f;
        if (kt == qt) {
            const int q0 = w*16 + rr, q1 = q0 + 8;
            #pragma unroll
            for (int j = 0; j < 8; j++) {
                const int c0 = 8*j + 2*cq, c1 = c0 + 1;
                if (c0 > q0) S[j][0] = -1e30f;
                if (c1 > q0) S[j][1] = -1e30f;
                if (c0 > q1) S[j][2] = -1e30f;
                if (c1 > q1) S[j][3] = -1e30f;
            }
        }

        // row max
        float t0 = -1e30f, t1 = -1e30f;
        #pragma unroll
        for (int j = 0; j < 8; j++) {
            t0 = fmaxf(t0, fmaxf(S[j][0], S[j][1]));
            t1 = fmaxf(t1, fmaxf(S[j][2], S[j][3]));
        }
        t0 = fmaxf(t0, __shfl_xor_sync(0xffffffffu, t0, 1));
        t0 = fmaxf(t0, __shfl_xor_sync(0xffffffffu, t0, 2));
        t1 = fmaxf(t1, __shfl_xor_sync(0xffffffffu, t1, 1));
        t1 = fmaxf(t1, __shfl_xor_sync(0xffffffffu, t1, 2));

        const float n0 = fmaxf(m0, t0), n1 = fmaxf(m1, t1);
        const float f0 = __expf(m0 - n0), f1 = __expf(m1 - n1);
        m0 = n0; m1 = n1;

        // p = exp(S - m), pack hi/lo A-frags, partial sums
        uint32_t ph[8][2], pl[8][2];
        float s0 = 0.f, s1 = 0.f;
        #pragma unroll
        for (int j = 0; j < 8; j++) {
            float p0 = __expf(S[j][0] - n0), p1 = __expf(S[j][1] - n0);
            float p2 = __expf(S[j][2] - n1), p3 = __expf(S[j][3] - n1);
            s0 += p0 + p1; s1 += p2 + p3;
            bf16 a,bl_,c,d;
            split1(p0,a,bl_); split1(p1,c,d);
            ph[j][0] = pack2(a,c); pl[j][0] = pack2(bl_,d);
            split1(p2,a,bl_); split1(p3,c,d);
            ph[j][1] = pack2(a,c); pl[j][1] = pack2(bl_,d);
        }
        s0 += __shfl_xor_sync(0xffffffffu, s0, 1);
        s0 += __shfl_xor_sync(0xffffffffu, s0, 2);
        s1 += __shfl_xor_sync(0xffffffffu, s1, 1);
        s1 += __shfl_xor_sync(0xffffffffu, s1, 2);
        l0 = l0*f0 + s0; l1 = l1*f1 + s1;

        // rescale O
        #pragma unroll
        for (int j = 0; j < 8; j++) {
            O[j][0] *= f0; O[j][1] *= f0; O[j][2] *= f1; O[j][3] *= f1;
        }

        // ---- O += P V (3-term split), V via ldmatrix.trans ----
        #pragma unroll
        for (int ks = 0; ks < 4; ks++) {
            uint32_t ah0 = ph[2*ks][0], ah1 = ph[2*ks][1],
                     ah2 = ph[2*ks+1][0], ah3 = ph[2*ks+1][1];
            uint32_t al0 = pl[2*ks][0], al1 = pl[2*ks][1],
                     al2 = pl[2*ks+1][0], al3 = pl[2*ks+1][1];
            #pragma unroll
            for (int j16 = 0; j16 < 4; j16++) {
                uint32_t rbv = (uint32_t)((ks*16 + lr)*AT_LDT + j16*16 + lc*8)*2;
                uint32_t v0,v1,v2,v3;
                ldmx4t(v0,v1,v2,v3, sVh + rbv);
                mma16816(O[2*j16],   ah0,ah1,ah2,ah3, v0,v1);
                mma16816(O[2*j16+1], ah0,ah1,ah2,ah3, v2,v3);
                mma16816(O[2*j16],   al0,al1,al2,al3, v0,v1);
                mma16816(O[2*j16+1], al0,al1,al2,al3, v2,v3);
                ldmx4t(v0,v1,v2,v3, sVl + rbv);
                mma16816(O[2*j16],   ah0,ah1,ah2,ah3, v0,v1);
                mma16816(O[2*j16+1], ah0,ah1,ah2,ah3, v2,v3);
            }
        }
        __syncthreads();
    }

    // epilogue: divide by l, split-store to g_oh/g_ol
    const float inv0 = 1.f / l0, inv1 = 1.f / l1;
    const size_t row0 = (size_t)(b*TT + qt*64 + w*16 + rr);
    const size_t row1 = row0 + 8;
    #pragma unroll
    for (int j = 0; j < 8; j++) {
        const int col = h*DD + 8*j + 2*cq;
        float e0 = O[j][0]*inv0, e1 = O[j][1]*inv0;
        float e2 = O[j][2]*inv1, e3 = O[j][3]*inv1;
        bf16 a,bl_,c,d;
        split1(e0,a,bl_); split1(e1,c,d);
        *(uint32_t*)(g_oh + row0*HH + col) = pack2(a,c);
        *(uint32_t*)(g_ol + row0*HH + col) = pack2(bl_,d);
        split1(e2,a,bl_); split1(e3,c,d);
        *(uint32_t*)(g_oh + row1*HH + col) = pack2(a,c);
        *(uint32_t*)(g_ol + row1*HH + col) = pack2(bl_,d);
    }
}

// ---------------- LayerNorm -------------------------------------------------
__global__ __launch_bounds__(256) void ln_kernel(
    const float* __restrict__ in, const float* __restrict__ gamma,
    const float* __restrict__ beta, float* __restrict__ out,
    bf16* __restrict__ outh, bf16* __restrict__ outl)
{
    __shared__ float red[256];
    const int row = blockIdx.x;
    const int tid = threadIdx.x;
    const float* p = in + (size_t)row * HH;

    float4 v = *(const float4*)(p + tid * 4);
    red[tid] = v.x + v.y + v.z + v.w;
    __syncthreads();
    #pragma unroll
    for (int off = 128; off > 0; off >>= 1) {
        if (tid < off) red[tid] += red[tid + off];
        __syncthreads();
    }
    const float mean = red[0] * (1.0f / HH);
    __syncthreads();

    float dx = v.x-mean, dy = v.y-mean, dz = v.z-mean, dw = v.w-mean;
    red[tid] = dx*dx + dy*dy + dz*dz + dw*dw;
    __syncthreads();
    #pragma unroll
    for (int off = 128; off > 0; off >>= 1) {
        if (tid < off) red[tid] += red[tid + off];
        __syncthreads();
    }
    const float rstd = rsqrtf(red[0] * (1.0f / HH) + 1e-5f);

    float4 g  = *(const float4*)(gamma + tid * 4);
    float4 be = *(const float4*)(beta + tid * 4);
    float4 rr;
    rr.x = dx*rstd*g.x + be.x;
    rr.y = dy*rstd*g.y + be.y;
    rr.z = dz*rstd*g.z + be.z;
    rr.w = dw*rstd*g.w + be.w;
    *(float4*)(out + (size_t)row*HH + tid*4) = rr;

    bf16 h0,h1,h2,h3,l0,l1,l2,l3;
    split1(rr.x,h0,l0); split1(rr.y,h1,l1); split1(rr.z,h2,l2); split1(rr.w,h3,l3);
    *(uint2*)(outh + (size_t)row*HH + tid*4) = make_uint2(pack2(h0,h1), pack2(h2,h3));
    *(uint2*)(outl + (size_t)row*HH + tid*4) = make_uint2(pack2(l0,l1), pack2(l2,l3));
}

// ---------------- launcher -------------------------------------------------
extern "C" void kernel_launch(void* const* d_in, const int* in_sizes, int n_in,
                              void* d_out, int out_size)
{
    const float* Wq  = (const float*)d_in[1];
    const float* bq  = (const float*)d_in[2];
    const float* Wk  = (const float*)d_in[3];
    const float* bk  = (const float*)d_in[4];
    const float* Wv  = (const float*)d_in[5];
    const float* bv  = (const float*)d_in[6];
    const float* Wp  = (const float*)d_in[7];
    const float* bp  = (const float*)d_in[8];
    const float* W1  = (const float*)d_in[9];
    const float* b1  = (const float*)d_in[10];
    const float* W2  = (const float*)d_in[11];
    const float* b2  = (const float*)d_in[12];
    const float* g1w = (const float*)d_in[13];
    const float* be1 = (const float*)d_in[14];
    const float* g2w = (const float*)d_in[15];
    const float* be2 = (const float*)d_in[16];

    cudaFuncSetAttribute(gemm_kernel, cudaFuncAttributeMaxDynamicSharedMemorySize, GEMM_SMEM);
    cudaFuncSetAttribute(attn_kernel, cudaFuncAttributeMaxDynamicSharedMemorySize, ATT_SMEM);

    float *gx, *gt;
    bf16 *gxh, *gxl, *gqkvh, *gqkvl, *goh, *gol, *ghh, *ghl;
    bf16 *wqh, *wql, *wph, *wpl, *w1h, *w1l, *w2h, *w2l;
    float *gbqkv;
    cudaGetSymbolAddress((void**)&gx,    g_x);
    cudaGetSymbolAddress((void**)&gxh,   g_xh);
    cudaGetSymbolAddress((void**)&gxl,   g_xl);
    cudaGetSymbolAddress((void**)&gqkvh, g_qkvh);
    cudaGetSymbolAddress((void**)&gqkvl, g_qkvl);
    cudaGetSymbolAddress((void**)&goh,   g_oh);
    cudaGetSymbolAddress((void**)&gol,   g_ol);
    cudaGetSymbolAddress((void**)&gt,    g_t);
    cudaGetSymbolAddress((void**)&ghh,   g_hh);
    cudaGetSymbolAddress((void**)&ghl,   g_hl);
    cudaGetSymbolAddress((void**)&wqh,   w_qkv_h);
    cudaGetSymbolAddress((void**)&wql,   w_qkv_l);
    cudaGetSymbolAddress((void**)&wph,   w_p_h);
    cudaGetSymbolAddress((void**)&wpl,   w_p_l);
    cudaGetSymbolAddress((void**)&w1h,   w_1_h);
    cudaGetSymbolAddress((void**)&w1l,   w_1_l);
    cudaGetSymbolAddress((void**)&w2h,   w_2_h);
    cudaGetSymbolAddress((void**)&w2l,   w_2_l);
    cudaGetSymbolAddress((void**)&gbqkv, g_bqkv);

    const dim3 tb(256);
    wsplit_kernel<<<dim3(HH/32, HH/32, LL), tb>>>(Wq, wqh,          wql,          HH, HH, (size_t)HH*HH, (size_t)H3*HH);
    wsplit_kernel<<<dim3(HH/32, HH/32, LL), tb>>>(Wk, wqh + HH*HH,  wql + HH*HH,  HH, HH, (size_t)HH*HH, (size_t)H3*HH);
    wsplit_kernel<<<dim3(HH/32, HH/32, LL), tb>>>(Wv, wqh + 2*HH*HH,wql + 2*HH*HH,HH, HH, (size_t)HH*HH, (size_t)H3*HH);
    wsplit_kernel<<<dim3(HH/32, HH/32, LL), tb>>>(Wp, wph, wpl, HH, HH, (size_t)HH*HH, (size_t)HH*HH);
    wsplit_kernel<<<dim3(FFF/32, HH/32, LL), tb>>>(W1, w1h, w1l, HH, FFF, (size_t)HH*FFF, (size_t)FFF*HH);
    wsplit_kernel<<<dim3(HH/32, FFF/32, LL), tb>>>(W2, w2h, w2l, FFF, HH, (size_t)FFF*HH, (size_t)HH*FFF);
    biaspack_kernel<<<(LL*H3 + 255)/256, 256>>>(bq, bk, bv);
    splitx_kernel<<<MM*HH/1024, 256>>>((const float*)d_in[0]);

    const dim3 gridQKV(H3/BN, MM/BM);
    const dim3 gridH(HH/BN, MM/BM);
    const dim3 gridF(FFF/BN, MM/BM);
    const dim3 gridA(TT/64, NHH, BB);

    for (int l = 0; l < LL; l++) {
        const size_t bo = (size_t)l * HH;

        // fused QKV projection -> split bf16
        gemm_kernel<<<gridQKV, 256, GEMM_SMEM>>>(
            gxh, gxl, wqh + (size_t)l*H3*HH, wql + (size_t)l*H3*HH,
            gbqkv + (size_t)l*H3, nullptr, nullptr, gqkvh, gqkvl,
            MM, H3, HH, 3);

        // tensor-core attention -> o split
        attn_kernel<<<gridA, 128, ATT_SMEM>>>(gqkvh, gqkvl);

        // output projection + residual ; LN1
        gemm_kernel<<<gridH, 256, GEMM_SMEM>>>(
            goh, gol, wph + (size_t)l*HH*HH, wpl + (size_t)l*HH*HH,
            bp + bo, gx, gt, nullptr, nullptr, MM, HH, HH, 2);
        ln_kernel<<<MM, 256>>>(gt, g1w + bo, be1 + bo, gx, gxh, gxl);

        // MLP
        gemm_kernel<<<gridF, 256, GEMM_SMEM>>>(
            gxh, gxl, w1h + (size_t)l*FFF*HH, w1l + (size_t)l*FFF*HH,
            b1 + (size_t)l*FFF, nullptr, nullptr, ghh, ghl, MM, FFF, HH, 1);
        gemm_kernel<<<gridH, 256, GEMM_SMEM>>>(
            ghh, ghl, w2h + (size_t)l*HH*FFF, w2l + (size_t)l*HH*FFF,
            b2 + bo, gx, gt, nullptr, nullptr, MM, HH, FFF, 2);
        ln_kernel<<<MM, 256>>>(gt, g2w + bo, be2 + bo, gx, gxh, gxl);
    }

    cudaMemcpyAsync(d_out, gx, (size_t)MM*HH*sizeof(float),
                    cudaMemcpyDeviceToDevice, 0);
}

// round 6
// speedup vs baseline: 2.5916x; 1.1911x over previous
#include <cuda_runtime.h>
#include <cuda_bf16.h>
#include <math.h>
#include <stdint.h>

#define BB 2
#define TT 2048
#define HH 1024
#define NHH 16
#define DD 64
#define FFF 4096
#define LL 6
#define MM (BB*TT)
#define H3 (3*HH)

typedef __nv_bfloat16 bf16;

// ---------------- device-global scratch ------------------------------------
__device__ float g_x [MM*HH];
__device__ bf16  g_xh[MM*HH];
__device__ bf16  g_xl[MM*HH];
__device__ bf16  g_qkvh[MM*H3];
__device__ bf16  g_qkvl[MM*H3];
__device__ bf16  g_oh[MM*HH];
__device__ bf16  g_ol[MM*HH];
__device__ float g_t [MM*HH];
__device__ bf16  g_hh[MM*FFF];
__device__ bf16  g_hl[MM*FFF];
__device__ bf16  w_qkv_h[LL*H3*HH],  w_qkv_l[LL*H3*HH];
__device__ bf16  w_p_h  [LL*HH*HH],  w_p_l  [LL*HH*HH];
__device__ bf16  w_1_h  [LL*FFF*HH], w_1_l  [LL*FFF*HH];
__device__ bf16  w_2_h  [LL*HH*FFF], w_2_l  [LL*HH*FFF];
__device__ float g_bqkv[LL*H3];

// ---------------- helpers ---------------------------------------------------
__device__ __forceinline__ void split1(float x, bf16& h, bf16& l) {
    h = __float2bfloat16_rn(x);
    l = __float2bfloat16_rn(x - __bfloat162float(h));
}
__device__ __forceinline__ uint32_t pack2(bf16 a, bf16 b) {
    return (uint32_t)__bfloat16_as_ushort(a) | ((uint32_t)__bfloat16_as_ushort(b) << 16);
}
__device__ __forceinline__ uint32_t smem_u32(const void* p) {
    return (uint32_t)__cvta_generic_to_shared(p);
}
__device__ __forceinline__ void cp16(uint32_t s, const void* g) {
    asm volatile("cp.async.cg.shared.global [%0],[%1],16;\n" :: "r"(s), "l"(g));
}
__device__ __forceinline__ void ldmx4(uint32_t& r0, uint32_t& r1, uint32_t& r2,
                                      uint32_t& r3, uint32_t addr) {
    asm volatile("ldmatrix.sync.aligned.m8n8.x4.shared.b16 {%0,%1,%2,%3},[%4];\n"
                 : "=r"(r0), "=r"(r1), "=r"(r2), "=r"(r3) : "r"(addr));
}
__device__ __forceinline__ void ldmx4t(uint32_t& r0, uint32_t& r1, uint32_t& r2,
                                       uint32_t& r3, uint32_t addr) {
    asm volatile("ldmatrix.sync.aligned.m8n8.x4.trans.shared.b16 {%0,%1,%2,%3},[%4];\n"
                 : "=r"(r0), "=r"(r1), "=r"(r2), "=r"(r3) : "r"(addr));
}
__device__ __forceinline__ void mma16816(float c[4], uint32_t a0, uint32_t a1,
                                         uint32_t a2, uint32_t a3,
                                         uint32_t b0, uint32_t b1) {
    asm volatile(
        "mma.sync.aligned.m16n8k16.row.col.f32.bf16.bf16.f32 "
        "{%0,%1,%2,%3}, {%4,%5,%6,%7}, {%8,%9}, {%0,%1,%2,%3};"
        : "+f"(c[0]), "+f"(c[1]), "+f"(c[2]), "+f"(c[3])
        : "r"(a0), "r"(a1), "r"(a2), "r"(a3), "r"(b0), "r"(b1));
}

// ---------------- weight transpose-split: src[K][N] -> dst[N][K] bf16 hi/lo -
__global__ __launch_bounds__(256) void wsplit_kernel(
    const float* __restrict__ src, bf16* __restrict__ dh, bf16* __restrict__ dl,
    int K, int N, size_t srcStride, size_t dstStride)
{
    __shared__ float t[32][33];
    const float* s = src + blockIdx.z * srcStride;
    const int n0 = blockIdx.x * 32, k0 = blockIdx.y * 32;
    const int tx = threadIdx.x & 31, ty = threadIdx.x >> 5;
    #pragma unroll
    for (int u = 0; u < 4; u++)
        t[ty + u * 8][tx] = s[(size_t)(k0 + ty + u * 8) * N + n0 + tx];
    __syncthreads();
    #pragma unroll
    for (int u = 0; u < 4; u++) {
        float v = t[tx][ty + u * 8];
        bf16 h, l; split1(v, h, l);
        size_t o = blockIdx.z * dstStride + (size_t)(n0 + ty + u * 8) * K + k0 + tx;
        dh[o] = h; dl[o] = l;
    }
}

__global__ void biaspack_kernel(const float* bq, const float* bk, const float* bv) {
    int idx = blockIdx.x * blockDim.x + threadIdx.x;
    if (idx >= LL * H3) return;
    int l = idx / H3, c = idx % H3;
    float v = (c < HH) ? bq[l*HH + c] : (c < 2*HH) ? bk[l*HH + c - HH] : bv[l*HH + c - 2*HH];
    g_bqkv[idx] = v;
}
__global__ void splitx_kernel(const float* __restrict__ in) {
    int id = blockIdx.x * blockDim.x + threadIdx.x;
    float4 v = *(const float4*)(in + (size_t)id * 4);
    *(float4*)(g_x + (size_t)id * 4) = v;
    bf16 h0,h1,h2,h3,l0,l1,l2,l3;
    split1(v.x,h0,l0); split1(v.y,h1,l1); split1(v.z,h2,l2); split1(v.w,h3,l3);
    *(uint2*)(g_xh + (size_t)id * 4) = make_uint2(pack2(h0,h1), pack2(h2,h3));
    *(uint2*)(g_xl + (size_t)id * 4) = make_uint2(pack2(l0,l1), pack2(l2,l3));
}

// ---------------- GEMM (mma.sync, swizzled smem, 3-stage pipeline) ----------
// epi: 0 bias->f32, 1 bias+gelu->split, 2 bias+resid->f32, 3 bias->split
#define BK 32
#define SUB 8192                    // bytes per sub-tile (128 rows x 32 bf16)
#define STAGE_B (4*SUB)             // Ah Al Bh Bl = 32 KB
#define GEMM_SMEM (3*STAGE_B)       // 96 KB

// swizzled byte offset for (row, 16B-chunk)
__device__ __forceinline__ uint32_t swz(int r, int c) {
    return (uint32_t)(r * 64 + ((c ^ ((r >> 1) & 3)) << 4));
}

__device__ __forceinline__ void ld_stage(
    uint32_t st, const bf16* Agh, const bf16* Agl,
    const bf16* Bgh, const bf16* Bgl,
    int bm, int bn, int K, int k0, int tid)
{
    #pragma unroll
    for (int u = tid; u < 512; u += 256) {
        const int r = u >> 2, c = u & 3;
        const uint32_t sw = swz(r, c);
        const size_t ga = (size_t)(bm + r) * K + k0 + c * 8;
        const size_t gb = (size_t)(bn + r) * K + k0 + c * 8;
        cp16(st + sw,           Agh + ga);
        cp16(st + SUB + sw,     Agl + ga);
        cp16(st + 2*SUB + sw,   Bgh + gb);
        cp16(st + 3*SUB + sw,   Bgl + gb);
    }
}

__global__ __launch_bounds__(256, 2) void gemm_kernel(
    const bf16* __restrict__ Agh, const bf16* __restrict__ Agl,
    const bf16* __restrict__ Bgh, const bf16* __restrict__ Bgl,
    const float* __restrict__ bias, const float* __restrict__ resid,
    float* __restrict__ C, bf16* __restrict__ Ch, bf16* __restrict__ Cl,
    int M, int N, int K, int epi)
{
    extern __shared__ __align__(16) bf16 sm[];
    const int tid  = threadIdx.x;
    const int lane = tid & 31;
    const int wid  = tid >> 5;
    const int warp_m = wid & 1;
    const int warp_n = wid >> 1;
    const int bm = blockIdx.y * 128;
    const int bn = blockIdx.x * 128;
    const uint32_t smB = smem_u32(sm);

    float acc[4][4][4];
    #pragma unroll
    for (int i = 0; i < 4; i++)
        #pragma unroll
        for (int j = 0; j < 4; j++)
            #pragma unroll
            for (int u = 0; u < 4; u++) acc[i][j][u] = 0.f;

    const int ntiles = K / BK;

    // prologue: stages 0 and 1
    ld_stage(smB, Agh, Agl, Bgh, Bgl, bm, bn, K, 0, tid);
    asm volatile("cp.async.commit_group;\n");
    if (ntiles > 1)
        ld_stage(smB + STAGE_B, Agh, Agl, Bgh, Bgl, bm, bn, K, BK, tid);
    asm volatile("cp.async.commit_group;\n");

    const int lr = lane & 15, lc = lane >> 4;

    for (int kt = 0; kt < ntiles; kt++) {
        asm volatile("cp.async.wait_group 1;\n");
        __syncthreads();

        const int nx = kt + 2;
        if (nx < ntiles)
            ld_stage(smB + (nx % 3) * STAGE_B, Agh, Agl, Bgh, Bgl,
                     bm, bn, K, nx * BK, tid);
        asm volatile("cp.async.commit_group;\n");

        const uint32_t st = smB + (kt % 3) * STAGE_B;
        const uint32_t Ah = st;
        const uint32_t Al = st + SUB;
        const uint32_t Bh = st + 2*SUB;
        const uint32_t Bl = st + 3*SUB;

        #pragma unroll
        for (int kk = 0; kk < 2; kk++) {
            const int cch = kk * 2 + lc;            // 16B chunk index 0..3
            uint32_t a[4][4], bh[4][2];
            // A-hi frags
            #pragma unroll
            for (int i = 0; i < 4; i++) {
                const int r_ = warp_m*64 + i*16 + lr;
                ldmx4(a[i][0], a[i][1], a[i][2], a[i][3], Ah + swz(r_, cch));
            }
            // B-hi frags
            #pragma unroll
            for (int j16 = 0; j16 < 2; j16++) {
                const int rb_ = warp_n*32 + j16*16 + lr;
                uint32_t r0, r1, r2, r3;
                ldmx4(r0, r1, r2, r3, Bh + swz(rb_, cch));
                bh[j16*2][0] = r0; bh[j16*2][1] = r2;
                bh[j16*2+1][0] = r1; bh[j16*2+1][1] = r3;
            }
            // term1: Ahi*Bhi
            #pragma unroll
            for (int i = 0; i < 4; i++)
                #pragma unroll
                for (int j = 0; j < 4; j++)
                    mma16816(acc[i][j], a[i][0],a[i][1],a[i][2],a[i][3], bh[j][0],bh[j][1]);
            // term2: Ahi*Blo
            {
                uint32_t bl[4][2];
                #pragma unroll
                for (int j16 = 0; j16 < 2; j16++) {
                    const int rb_ = warp_n*32 + j16*16 + lr;
                    uint32_t r0, r1, r2, r3;
                    ldmx4(r0, r1, r2, r3, Bl + swz(rb_, cch));
                    bl[j16*2][0] = r0; bl[j16*2][1] = r2;
                    bl[j16*2+1][0] = r1; bl[j16*2+1][1] = r3;
                }
                #pragma unroll
                for (int i = 0; i < 4; i++)
                    #pragma unroll
                    for (int j = 0; j < 4; j++)
                        mma16816(acc[i][j], a[i][0],a[i][1],a[i][2],a[i][3], bl[j][0],bl[j][1]);
            }
            // term3: Alo*Bhi (overwrite dead A-hi regs)
            #pragma unroll
            for (int i = 0; i < 4; i++) {
                const int r_ = warp_m*64 + i*16 + lr;
                ldmx4(a[i][0], a[i][1], a[i][2], a[i][3], Al + swz(r_, cch));
            }
            #pragma unroll
            for (int i = 0; i < 4; i++)
                #pragma unroll
                for (int j = 0; j < 4; j++)
                    mma16816(acc[i][j], a[i][0],a[i][1],a[i][2],a[i][3], bh[j][0],bh[j][1]);
        }
    }

    // ---- epilogue (direct from acc frags) ----
    #pragma unroll
    for (int i = 0; i < 4; i++) {
        #pragma unroll
        for (int j = 0; j < 4; j++) {
            const int row0 = bm + warp_m*64 + i*16 + (lane >> 2);
            const int col  = bn + warp_n*32 + j*8 + 2*(lane & 3);
            const float2 bv = *(const float2*)(bias + col);
            #pragma unroll
            for (int half = 0; half < 2; half++) {
                const int row = row0 + half * 8;
                float rx = acc[i][j][half*2+0] + bv.x;
                float ry = acc[i][j][half*2+1] + bv.y;
                if (epi == 1) {
                    rx = 0.5f * rx * (1.0f + erff(rx * 0.70710678118654752f));
                    ry = 0.5f * ry * (1.0f + erff(ry * 0.70710678118654752f));
                }
                if (epi == 1 || epi == 3) {
                    bf16 hx,lx,hy,ly;
                    split1(rx,hx,lx); split1(ry,hy,ly);
                    *(uint32_t*)(Ch + (size_t)row*N + col) = pack2(hx,hy);
                    *(uint32_t*)(Cl + (size_t)row*N + col) = pack2(lx,ly);
                } else if (epi == 2) {
                    const float2 rv = *(const float2*)(resid + (size_t)row*N + col);
                    *(float2*)(C + (size_t)row*N + col) = make_float2(rx + rv.x, ry + rv.y);
                } else {
                    *(float2*)(C + (size_t)row*N + col) = make_float2(rx, ry);
                }
            }
        }
    }
}

// ---------------- tensor-core causal flash attention ------------------------
#define AT_LDT 72
#define AT_TILE (64*AT_LDT)
#define ATT_SMEM (6*AT_TILE*2)

__global__ __launch_bounds__(128, 4) void attn_kernel(
    const bf16* __restrict__ QKVh, const bf16* __restrict__ QKVl)
{
    extern __shared__ __align__(16) bf16 asmem[];
    const uint32_t sQh = smem_u32(asmem);
    const uint32_t sQl = sQh + AT_TILE*2;
    const uint32_t sKh = sQh + 2*AT_TILE*2;
    const uint32_t sKl = sQh + 3*AT_TILE*2;
    const uint32_t sVh = sQh + 4*AT_TILE*2;
    const uint32_t sVl = sQh + 5*AT_TILE*2;

    const int qt  = blockIdx.x;
    const int h   = blockIdx.y;
    const int b   = blockIdx.z;
    const int tid = threadIdx.x;
    const int w    = tid >> 5;
    const int lane = tid & 31;
    const int lr = lane & 15, lc = lane >> 4;
    const int rr = lane >> 2, cq = lane & 3;

    #pragma unroll
    for (int c = tid; c < 512; c += 128) {
        int row = c >> 3, seg = c & 7;
        size_t g = ((size_t)(b*TT + qt*64 + row))*H3 + h*DD + seg*8;
        uint32_t s = (uint32_t)(row*AT_LDT + seg*8)*2;
        cp16(sQh + s, QKVh + g);
        cp16(sQl + s, QKVl + g);
    }
    asm volatile("cp.async.commit_group;\n");

    float O[8][4];
    #pragma unroll
    for (int j = 0; j < 8; j++)
        #pragma unroll
        for (int u = 0; u < 4; u++) O[j][u] = 0.f;
    float m0 = -1e30f, m1 = -1e30f, l0 = 0.f, l1 = 0.f;

    for (int kt = 0; kt <= qt; kt++) {
        #pragma unroll
        for (int c = tid; c < 512; c += 128) {
            int row = c >> 3, seg = c & 7;
            size_t gk = ((size_t)(b*TT + kt*64 + row))*H3 + HH + h*DD + seg*8;
            uint32_t s = (uint32_t)(row*AT_LDT + seg*8)*2;
            cp16(sKh + s, QKVh + gk);
            cp16(sKl + s, QKVl + gk);
            cp16(sVh + s, QKVh + gk + HH);
            cp16(sVl + s, QKVl + gk + HH);
        }
        asm volatile("cp.async.commit_group;\n");
        asm volatile("cp.async.wait_group 0;\n");
        __syncthreads();

        float S[8][4];
        #pragma unroll
        for (int j = 0; j < 8; j++)
            #pragma unroll
            for (int u = 0; u < 4; u++) S[j][u] = 0.f;

        #pragma unroll
        for (int ks = 0; ks < 4; ks++) {
            const uint32_t coff = (uint32_t)(ks*16 + lc*8)*2;
            uint32_t qh[4], ql[4];
            uint32_t ra = (uint32_t)((w*16 + lr)*AT_LDT)*2 + coff;
            ldmx4(qh[0], qh[1], qh[2], qh[3], sQh + ra);
            ldmx4(ql[0], ql[1], ql[2], ql[3], sQl + ra);
            #pragma unroll
            for (int j16 = 0; j16 < 4; j16++) {
                uint32_t rb = (uint32_t)((j16*16 + lr)*AT_LDT)*2 + coff;
                uint32_t k0,k1,k2,k3;
                ldmx4(k0,k1,k2,k3, sKh + rb);
                mma16816(S[j16*2],   qh[0],qh[1],qh[2],qh[3], k0,k2);
                mma16816(S[j16*2+1], qh[0],qh[1],qh[2],qh[3], k1,k3);
                mma16816(S[j16*2],   ql[0],ql[1],ql[2],ql[3], k0,k2);
                mma16816(S[j16*2+1], ql[0],ql[1],ql[2],ql[3], k1,k3);
                ldmx4(k0,k1,k2,k3, sKl + rb);
                mma16816(S[j16*2],   qh[0],qh[1],qh[2],qh[3], k0,k2);
                mma16816(S[j16*2+1], qh[0],qh[1],qh[2],qh[3], k1,k3);
            }
        }

        #pragma unroll
        for (int j = 0; j < 8; j++)
            #pragma unroll
            for (int u = 0; u < 4; u++) S[j][u] *= 0.125f;
        if (kt == qt) {
            const int q0 = w*16 + rr, q1 = q0 + 8;
            #pragma unroll
            for (int j = 0; j < 8; j++) {
                const int c0 = 8*j + 2*cq, c1 = c0 + 1;
                if (c0 > q0) S[j][0] = -1e30f;
                if (c1 > q0) S[j][1] = -1e30f;
                if (c0 > q1) S[j][2] = -1e30f;
                if (c1 > q1) S[j][3] = -1e30f;
            }
        }

        float t0 = -1e30f, t1 = -1e30f;
        #pragma unroll
        for (int j = 0; j < 8; j++) {
            t0 = fmaxf(t0, fmaxf(S[j][0], S[j][1]));
            t1 = fmaxf(t1, fmaxf(S[j][2], S[j][3]));
        }
        t0 = fmaxf(t0, __shfl_xor_sync(0xffffffffu, t0, 1));
        t0 = fmaxf(t0, __shfl_xor_sync(0xffffffffu, t0, 2));
        t1 = fmaxf(t1, __shfl_xor_sync(0xffffffffu, t1, 1));
        t1 = fmaxf(t1, __shfl_xor_sync(0xffffffffu, t1, 2));

        const float n0 = fmaxf(m0, t0), n1 = fmaxf(m1, t1);
        const float f0 = __expf(m0 - n0), f1 = __expf(m1 - n1);
        m0 = n0; m1 = n1;

        uint32_t ph[8][2], pl[8][2];
        float s0 = 0.f, s1 = 0.f;
        #pragma unroll
        for (int j = 0; j < 8; j++) {
            float p0 = __expf(S[j][0] - n0), p1 = __expf(S[j][1] - n0);
            float p2 = __expf(S[j][2] - n1), p3 = __expf(S[j][3] - n1);
            s0 += p0 + p1; s1 += p2 + p3;
            bf16 a,bl_,c,d;
            split1(p0,a,bl_); split1(p1,c,d);
            ph[j][0] = pack2(a,c); pl[j][0] = pack2(bl_,d);
            split1(p2,a,bl_); split1(p3,c,d);
            ph[j][1] = pack2(a,c); pl[j][1] = pack2(bl_,d);
        }
        s0 += __shfl_xor_sync(0xffffffffu, s0, 1);
        s0 += __shfl_xor_sync(0xffffffffu, s0, 2);
        s1 += __shfl_xor_sync(0xffffffffu, s1, 1);
        s1 += __shfl_xor_sync(0xffffffffu, s1, 2);
        l0 = l0*f0 + s0; l1 = l1*f1 + s1;

        #pragma unroll
        for (int j = 0; j < 8; j++) {
            O[j][0] *= f0; O[j][1] *= f0; O[j][2] *= f1; O[j][3] *= f1;
        }

        #pragma unroll
        for (int ks = 0; ks < 4; ks++) {
            uint32_t ah0 = ph[2*ks][0], ah1 = ph[2*ks][1],
                     ah2 = ph[2*ks+1][0], ah3 = ph[2*ks+1][1];
            uint32_t al0 = pl[2*ks][0], al1 = pl[2*ks][1],
                     al2 = pl[2*ks+1][0], al3 = pl[2*ks+1][1];
            #pragma unroll
            for (int j16 = 0; j16 < 4; j16++) {
                uint32_t rbv = (uint32_t)((ks*16 + lr)*AT_LDT + j16*16 + lc*8)*2;
                uint32_t v0,v1,v2,v3;
                ldmx4t(v0,v1,v2,v3, sVh + rbv);
                mma16816(O[2*j16],   ah0,ah1,ah2,ah3, v0,v1);
                mma16816(O[2*j16+1], ah0,ah1,ah2,ah3, v2,v3);
                mma16816(O[2*j16],   al0,al1,al2,al3, v0,v1);
                mma16816(O[2*j16+1], al0,al1,al2,al3, v2,v3);
                ldmx4t(v0,v1,v2,v3, sVl + rbv);
                mma16816(O[2*j16],   ah0,ah1,ah2,ah3, v0,v1);
                mma16816(O[2*j16+1], ah0,ah1,ah2,ah3, v2,v3);
            }
        }
        __syncthreads();
    }

    const float inv0 = 1.f / l0, inv1 = 1.f / l1;
    const size_t row0 = (size_t)(b*TT + qt*64 + w*16 + rr);
    const size_t row1 = row0 + 8;
    #pragma unroll
    for (int j = 0; j < 8; j++) {
        const int col = h*DD + 8*j + 2*cq;
        float e0 = O[j][0]*inv0, e1 = O[j][1]*inv0;
        float e2 = O[j][2]*inv1, e3 = O[j][3]*inv1;
        bf16 a,bl_,c,d;
        split1(e0,a,bl_); split1(e1,c,d);
        *(uint32_t*)(g_oh + row0*HH + col) = pack2(a,c);
        *(uint32_t*)(g_ol + row0*HH + col) = pack2(bl_,d);
        split1(e2,a,bl_); split1(e3,c,d);
        *(uint32_t*)(g_oh + row1*HH + col) = pack2(a,c);
        *(uint32_t*)(g_ol + row1*HH + col) = pack2(bl_,d);
    }
}

// ---------------- LayerNorm -------------------------------------------------
__global__ __launch_bounds__(256) void ln_kernel(
    const float* __restrict__ in, const float* __restrict__ gamma,
    const float* __restrict__ beta, float* __restrict__ out,
    bf16* __restrict__ outh, bf16* __restrict__ outl)
{
    __shared__ float red[256];
    const int row = blockIdx.x;
    const int tid = threadIdx.x;
    const float* p = in + (size_t)row * HH;

    float4 v = *(const float4*)(p + tid * 4);
    red[tid] = v.x + v.y + v.z + v.w;
    __syncthreads();
    #pragma unroll
    for (int off = 128; off > 0; off >>= 1) {
        if (tid < off) red[tid] += red[tid + off];
        __syncthreads();
    }
    const float mean = red[0] * (1.0f / HH);
    __syncthreads();

    float dx = v.x-mean, dy = v.y-mean, dz = v.z-mean, dw = v.w-mean;
    red[tid] = dx*dx + dy*dy + dz*dz + dw*dw;
    __syncthreads();
    #pragma unroll
    for (int off = 128; off > 0; off >>= 1) {
        if (tid < off) red[tid] += red[tid + off];
        __syncthreads();
    }
    const float rstd = rsqrtf(red[0] * (1.0f / HH) + 1e-5f);

    float4 g  = *(const float4*)(gamma + tid * 4);
    float4 be = *(const float4*)(beta + tid * 4);
    float4 rr;
    rr.x = dx*rstd*g.x + be.x;
    rr.y = dy*rstd*g.y + be.y;
    rr.z = dz*rstd*g.z + be.z;
    rr.w = dw*rstd*g.w + be.w;
    *(float4*)(out + (size_t)row*HH + tid*4) = rr;

    bf16 h0,h1,h2,h3,l0,l1,l2,l3;
    split1(rr.x,h0,l0); split1(rr.y,h1,l1); split1(rr.z,h2,l2); split1(rr.w,h3,l3);
    *(uint2*)(outh + (size_t)row*HH + tid*4) = make_uint2(pack2(h0,h1), pack2(h2,h3));
    *(uint2*)(outl + (size_t)row*HH + tid*4) = make_uint2(pack2(l0,l1), pack2(l2,l3));
}

// ---------------- launcher -------------------------------------------------
extern "C" void kernel_launch(void* const* d_in, const int* in_sizes, int n_in,
                              void* d_out, int out_size)
{
    const float* Wq  = (const float*)d_in[1];
    const float* bq  = (const float*)d_in[2];
    const float* Wk  = (const float*)d_in[3];
    const float* bk  = (const float*)d_in[4];
    const float* Wv  = (const float*)d_in[5];
    const float* bv  = (const float*)d_in[6];
    const float* Wp  = (const float*)d_in[7];
    const float* bp  = (const float*)d_in[8];
    const float* W1  = (const float*)d_in[9];
    const float* b1  = (const float*)d_in[10];
    const float* W2  = (const float*)d_in[11];
    const float* b2  = (const float*)d_in[12];
    const float* g1w = (const float*)d_in[13];
    const float* be1 = (const float*)d_in[14];
    const float* g2w = (const float*)d_in[15];
    const float* be2 = (const float*)d_in[16];

    cudaFuncSetAttribute(gemm_kernel, cudaFuncAttributeMaxDynamicSharedMemorySize, GEMM_SMEM);
    cudaFuncSetAttribute(attn_kernel, cudaFuncAttributeMaxDynamicSharedMemorySize, ATT_SMEM);

    float *gx, *gt;
    bf16 *gxh, *gxl, *gqkvh, *gqkvl, *goh, *gol, *ghh, *ghl;
    bf16 *wqh, *wql, *wph, *wpl, *w1h, *w1l, *w2h, *w2l;
    float *gbqkv;
    cudaGetSymbolAddress((void**)&gx,    g_x);
    cudaGetSymbolAddress((void**)&gxh,   g_xh);
    cudaGetSymbolAddress((void**)&gxl,   g_xl);
    cudaGetSymbolAddress((void**)&gqkvh, g_qkvh);
    cudaGetSymbolAddress((void**)&gqkvl, g_qkvl);
    cudaGetSymbolAddress((void**)&goh,   g_oh);
    cudaGetSymbolAddress((void**)&gol,   g_ol);
    cudaGetSymbolAddress((void**)&gt,    g_t);
    cudaGetSymbolAddress((void**)&ghh,   g_hh);
    cudaGetSymbolAddress((void**)&ghl,   g_hl);
    cudaGetSymbolAddress((void**)&wqh,   w_qkv_h);
    cudaGetSymbolAddress((void**)&wql,   w_qkv_l);
    cudaGetSymbolAddress((void**)&wph,   w_p_h);
    cudaGetSymbolAddress((void**)&wpl,   w_p_l);
    cudaGetSymbolAddress((void**)&w1h,   w_1_h);
    cudaGetSymbolAddress((void**)&w1l,   w_1_l);
    cudaGetSymbolAddress((void**)&w2h,   w_2_h);
    cudaGetSymbolAddress((void**)&w2l,   w_2_l);
    cudaGetSymbolAddress((void**)&gbqkv, g_bqkv);

    const dim3 tb(256);
    wsplit_kernel<<<dim3(HH/32, HH/32, LL), tb>>>(Wq, wqh,          wql,          HH, HH, (size_t)HH*HH, (size_t)H3*HH);
    wsplit_kernel<<<dim3(HH/32, HH/32, LL), tb>>>(Wk, wqh + HH*HH,  wql + HH*HH,  HH, HH, (size_t)HH*HH, (size_t)H3*HH);
    wsplit_kernel<<<dim3(HH/32, HH/32, LL), tb>>>(Wv, wqh + 2*HH*HH,wql + 2*HH*HH,HH, HH, (size_t)HH*HH, (size_t)H3*HH);
    wsplit_kernel<<<dim3(HH/32, HH/32, LL), tb>>>(Wp, wph, wpl, HH, HH, (size_t)HH*HH, (size_t)HH*HH);
    wsplit_kernel<<<dim3(FFF/32, HH/32, LL), tb>>>(W1, w1h, w1l, HH, FFF, (size_t)HH*FFF, (size_t)FFF*HH);
    wsplit_kernel<<<dim3(HH/32, FFF/32, LL), tb>>>(W2, w2h, w2l, FFF, HH, (size_t)FFF*HH, (size_t)HH*FFF);
    biaspack_kernel<<<(LL*H3 + 255)/256, 256>>>(bq, bk, bv);
    splitx_kernel<<<MM*HH/1024, 256>>>((const float*)d_in[0]);

    const dim3 gridQKV(H3/128, MM/128);   // (24, 32)
    const dim3 gridH(HH/128, MM/128);     // (8, 32)
    const dim3 gridF(FFF/128, MM/128);    // (32, 32)
    const dim3 gridA(TT/64, NHH, BB);

    for (int l = 0; l < LL; l++) {
        const size_t bo = (size_t)l * HH;

        gemm_kernel<<<gridQKV, 256, GEMM_SMEM>>>(
            gxh, gxl, wqh + (size_t)l*H3*HH, wql + (size_t)l*H3*HH,
            gbqkv + (size_t)l*H3, nullptr, nullptr, gqkvh, gqkvl,
            MM, H3, HH, 3);

        attn_kernel<<<gridA, 128, ATT_SMEM>>>(gqkvh, gqkvl);

        gemm_kernel<<<gridH, 256, GEMM_SMEM>>>(
            goh, gol, wph + (size_t)l*HH*HH, wpl + (size_t)l*HH*HH,
            bp + bo, gx, gt, nullptr, nullptr, MM, HH, HH, 2);
        ln_kernel<<<MM, 256>>>(gt, g1w + bo, be1 + bo, gx, gxh, gxl);

        gemm_kernel<<<gridF, 256, GEMM_SMEM>>>(
            gxh, gxl, w1h + (size_t)l*FFF*HH, w1l + (size_t)l*FFF*HH,
            b1 + (size_t)l*FFF, nullptr, nullptr, ghh, ghl, MM, FFF, HH, 1);
        gemm_kernel<<<gridH, 256, GEMM_SMEM>>>(
            ghh, ghl, w2h + (size_t)l*HH*FFF, w2l + (size_t)l*HH*FFF,
            b2 + bo, gx, gt, nullptr, nullptr, MM, HH, FFF, 2);
        ln_kernel<<<MM, 256>>>(gt, g2w + bo, be2 + bo, gx, gxh, gxl);
    }

    cudaMemcpyAsync(d_out, gx, (size_t)MM*HH*sizeof(float),
                    cudaMemcpyDeviceToDevice, 0);
}